// round 2
// baseline (speedup 1.0000x reference)
#include <cuda_runtime.h>

#define EMBED  1024
#define NHEADS 16
#define HDIM   64
#define BATCH  4
#define SEQ    2048
#define MROWS  (BATCH*SEQ)   /* 8192 */

// Scratch (static __device__, no allocation)
__device__ float g_Q [BATCH*NHEADS*SEQ*HDIM];   // (b,h,s,d)
__device__ float g_Kt[BATCH*NHEADS*HDIM*SEQ];   // (b,h,d,s)  -- transposed K
__device__ float g_V [BATCH*NHEADS*SEQ*HDIM];   // (b,h,s,d)
__device__ float g_O [BATCH*SEQ*EMBED];         // (b,s,e)

__device__ __forceinline__ float ex2a(float x){
    float y; asm("ex2.approx.f32 %0, %1;" : "=f"(y) : "f"(x)); return y;
}

// ---------------------------------------------------------------------------
// QKV GEMM:  (8192 x 1024) @ (1024 x 3072) + bias, scattered into g_Q/g_Kt/g_V
// 128x128 tile, BK=8, 256 threads, 8x8 per thread (4+4 split)
// ---------------------------------------------------------------------------
__global__ __launch_bounds__(256) void qkv_gemm(const float* __restrict__ X,
                                                const float* __restrict__ W,
                                                const float* __restrict__ bias)
{
    const int KD = EMBED;
    const int N  = 3*EMBED;
    __shared__ float As[8*132];
    __shared__ float Bs[8*132];
    const int tid = threadIdx.x;
    const int tx = tid & 15, ty = tid >> 4;
    const int m0 = blockIdx.y * 128;
    const int n0 = blockIdx.x * 128;

    float acc[8][8];
#pragma unroll
    for (int i=0;i<8;i++)
#pragma unroll
        for (int j=0;j<8;j++) acc[i][j]=0.f;

    const int arow = tid >> 1, acol = (tid & 1)*4;
    const int brow = tid >> 5, bcol = (tid & 31)*4;
    const float* Ap = X + (size_t)(m0+arow)*KD + acol;
    const float* Bp = W + (size_t)brow*N + n0 + bcol;

    for (int kt=0; kt<KD; kt+=8){
        float4 av = *(const float4*)(Ap + kt);
        float4 bv = *(const float4*)(Bp + (size_t)kt*N);
        As[(acol+0)*132+arow]=av.x;
        As[(acol+1)*132+arow]=av.y;
        As[(acol+2)*132+arow]=av.z;
        As[(acol+3)*132+arow]=av.w;
        *(float4*)&Bs[brow*132+bcol]=bv;
        __syncthreads();
#pragma unroll
        for (int k=0;k<8;k++){
            float4 a0=*(float4*)&As[k*132+ty*4];
            float4 a1=*(float4*)&As[k*132+64+ty*4];
            float4 b0=*(float4*)&Bs[k*132+tx*4];
            float4 b1=*(float4*)&Bs[k*132+64+tx*4];
            float ar[8]={a0.x,a0.y,a0.z,a0.w,a1.x,a1.y,a1.z,a1.w};
            float br[8]={b0.x,b0.y,b0.z,b0.w,b1.x,b1.y,b1.z,b1.w};
#pragma unroll
            for (int i=0;i<8;i++)
#pragma unroll
                for (int j=0;j<8;j++) acc[i][j]=fmaf(ar[i],br[j],acc[i][j]);
        }
        __syncthreads();
    }

    // Epilogue: scatter into Q (b,h,s,d) / Kt (b,h,d,s) / V (b,h,s,d)
#pragma unroll
    for (int gj=0; gj<2; gj++){
        const int n     = n0 + gj*64 + tx*4;
        const int three = n >> 10;
        const int rr    = n & 1023;
        const int h     = rr >> 6;
        const int d     = rr & 63;
        const float4 bs4 = *(const float4*)&bias[n];
        const float bsc[4] = {bs4.x, bs4.y, bs4.z, bs4.w};
#pragma unroll
        for (int gi=0; gi<2; gi++){
            const int row0 = m0 + gi*64 + ty*4;
            const int bb   = row0 >> 11;       // batch
            const int s0   = row0 & 2047;      // seq within batch
            if (three == 1) {
                // K transposed: column of 4 consecutive seq positions
#pragma unroll
                for (int jj=0;jj<4;jj++){
                    float4 v;
                    v.x = acc[gi*4+0][gj*4+jj] + bsc[jj];
                    v.y = acc[gi*4+1][gj*4+jj] + bsc[jj];
                    v.z = acc[gi*4+2][gj*4+jj] + bsc[jj];
                    v.w = acc[gi*4+3][gj*4+jj] + bsc[jj];
                    *(float4*)&g_Kt[(((size_t)(bb*NHEADS + h)*HDIM) + d + jj)*SEQ + s0] = v;
                }
            } else {
                float* dst = (three == 0) ? g_Q : g_V;
#pragma unroll
                for (int ii=0; ii<4; ii++){
                    float4 v;
                    v.x = acc[gi*4+ii][gj*4+0] + bs4.x;
                    v.y = acc[gi*4+ii][gj*4+1] + bs4.y;
                    v.z = acc[gi*4+ii][gj*4+2] + bs4.z;
                    v.w = acc[gi*4+ii][gj*4+3] + bs4.w;
                    *(float4*)&dst[((size_t)(bb*NHEADS + h)*SEQ + s0 + ii)*HDIM + d] = v;
                }
            }
        }
    }
}

// ---------------------------------------------------------------------------
// Fused flash attention: per (b,h,qblock of 64), iterate 32 key tiles of 64.
// 256 threads; thread (tx,ty) owns a 4x4 score quad and a 4x4 O quad.
// ---------------------------------------------------------------------------
__global__ __launch_bounds__(256) void attn_kernel(const int* __restrict__ mask)
{
    extern __shared__ float smem[];
    float* Qs = smem;              // [64][68]
    float* Ks = smem + 4352;       // [d][key]  [64][68]
    float* Vs = smem + 8704;       // [key][d]  [64][68]
    float* Ps = smem + 13056;      // [64][68]

    const int qb = blockIdx.x;     // 0..31
    const int h  = blockIdx.y;
    const int bb = blockIdx.z;
    const int tid = threadIdx.x;
    const int tx = tid & 15, ty = tid >> 4;

    const float* Qg = g_Q  + ((size_t)(bb*NHEADS + h)*SEQ + qb*64)*HDIM;
    const float* Kg = g_Kt +  (size_t)(bb*NHEADS + h)*HDIM*SEQ;
    const float* Vg = g_V  +  (size_t)(bb*NHEADS + h)*SEQ*HDIM;
    const int*   Mg = mask +  ((size_t)bb*SEQ + qb*64)*SEQ;

    // load Q tile (stays resident)
    for (int u = tid; u < 64*16; u += 256){
        int r = u >> 4, c4 = (u & 15)*4;
        *(float4*)&Qs[r*68 + c4] = *(const float4*)&Qg[r*64 + c4];
    }

    float o[4][4];
#pragma unroll
    for (int i=0;i<4;i++)
#pragma unroll
        for (int j=0;j<4;j++) o[i][j]=0.f;
    float m_i[4] = {-1e30f,-1e30f,-1e30f,-1e30f};
    float l_i[4] = {0.f,0.f,0.f,0.f};

    const float CE = 0.18033688011112042f;   // log2(e) / sqrt(64)

    for (int kt = 0; kt < SEQ/64; kt++){
        const int k0 = kt*64;
        __syncthreads();   // previous-iteration readers of Ks/Vs/Ps done
        for (int u = tid; u < 64*16; u += 256){
            int r = u >> 4, c4 = (u & 15)*4;
            *(float4*)&Ks[r*68 + c4] = *(const float4*)&Kg[(size_t)r*SEQ + k0 + c4];
            *(float4*)&Vs[r*68 + c4] = *(const float4*)&Vg[(size_t)(k0+r)*HDIM + c4];
        }
        __syncthreads();

        // S = Q @ K^T   (K stored d-major: Ks[d][key])
        float sc[4][4];
#pragma unroll
        for (int i=0;i<4;i++)
#pragma unroll
            for (int j=0;j<4;j++) sc[i][j]=0.f;
#pragma unroll
        for (int d4=0; d4<64; d4+=4){
            float qa[4][4];
#pragma unroll
            for (int i=0;i<4;i++)
                *(float4*)qa[i] = *(const float4*)&Qs[(ty*4+i)*68 + d4];
#pragma unroll
            for (int dd=0; dd<4; dd++){
                float4 kv = *(const float4*)&Ks[(d4+dd)*68 + tx*4];
#pragma unroll
                for (int i=0;i<4;i++){
                    sc[i][0]=fmaf(qa[i][dd],kv.x,sc[i][0]);
                    sc[i][1]=fmaf(qa[i][dd],kv.y,sc[i][1]);
                    sc[i][2]=fmaf(qa[i][dd],kv.z,sc[i][2]);
                    sc[i][3]=fmaf(qa[i][dd],kv.w,sc[i][3]);
                }
            }
        }

        // mask + online softmax (scale folded into exp2 argument)
#pragma unroll
        for (int i=0;i<4;i++){
            const int4 mv = *(const int4*)(Mg + (size_t)(ty*4+i)*SEQ + k0 + tx*4);
            if (mv.x == 0) sc[i][0] = -1e30f;
            if (mv.y == 0) sc[i][1] = -1e30f;
            if (mv.z == 0) sc[i][2] = -1e30f;
            if (mv.w == 0) sc[i][3] = -1e30f;
            float rm = fmaxf(fmaxf(sc[i][0],sc[i][1]), fmaxf(sc[i][2],sc[i][3]));
            rm = fmaxf(rm, __shfl_xor_sync(0xffffffffu, rm, 1));
            rm = fmaxf(rm, __shfl_xor_sync(0xffffffffu, rm, 2));
            rm = fmaxf(rm, __shfl_xor_sync(0xffffffffu, rm, 4));
            rm = fmaxf(rm, __shfl_xor_sync(0xffffffffu, rm, 8));
            const float mn = fmaxf(m_i[i], rm);
            const float alpha = ex2a((m_i[i] - mn) * CE);
            m_i[i] = mn;
            float rs = 0.f;
#pragma unroll
            for (int j=0;j<4;j++){
                float p = ex2a((sc[i][j] - mn) * CE);
                sc[i][j] = p; rs += p;
            }
            rs += __shfl_xor_sync(0xffffffffu, rs, 1);
            rs += __shfl_xor_sync(0xffffffffu, rs, 2);
            rs += __shfl_xor_sync(0xffffffffu, rs, 4);
            rs += __shfl_xor_sync(0xffffffffu, rs, 8);
            l_i[i] = l_i[i]*alpha + rs;
#pragma unroll
            for (int j=0;j<4;j++) o[i][j] *= alpha;
            *(float4*)&Ps[(ty*4+i)*68 + tx*4] =
                make_float4(sc[i][0],sc[i][1],sc[i][2],sc[i][3]);
        }
        __syncthreads();

        // O += P @ V
#pragma unroll
        for (int k4=0; k4<64; k4+=4){
            float pa[4][4];
#pragma unroll
            for (int i=0;i<4;i++)
                *(float4*)pa[i] = *(const float4*)&Ps[(ty*4+i)*68 + k4];
#pragma unroll
            for (int kk=0; kk<4; kk++){
                float4 vv = *(const float4*)&Vs[(k4+kk)*68 + tx*4];
#pragma unroll
                for (int i=0;i<4;i++){
                    o[i][0]=fmaf(pa[i][kk],vv.x,o[i][0]);
                    o[i][1]=fmaf(pa[i][kk],vv.y,o[i][1]);
                    o[i][2]=fmaf(pa[i][kk],vv.z,o[i][2]);
                    o[i][3]=fmaf(pa[i][kk],vv.w,o[i][3]);
                }
            }
        }
    }

    // epilogue: O / l, write to (b,s,e) with e = h*64 + d
#pragma unroll
    for (int i=0;i<4;i++){
        const float inv = 1.0f / l_i[i];
        const int qrow = qb*64 + ty*4 + i;
        *(float4*)&g_O[((size_t)bb*SEQ + qrow)*EMBED + h*HDIM + tx*4] =
            make_float4(o[i][0]*inv, o[i][1]*inv, o[i][2]*inv, o[i][3]*inv);
    }
}

// ---------------------------------------------------------------------------
// Output projection: (8192 x 1024) @ (1024 x 1024) + bias -> d_out
// ---------------------------------------------------------------------------
__global__ __launch_bounds__(256) void out_gemm(const float* __restrict__ W,
                                                const float* __restrict__ bias,
                                                float* __restrict__ out)
{
    const int KD = EMBED;
    const int N  = EMBED;
    __shared__ float As[8*132];
    __shared__ float Bs[8*132];
    const int tid = threadIdx.x;
    const int tx = tid & 15, ty = tid >> 4;
    const int m0 = blockIdx.y * 128;
    const int n0 = blockIdx.x * 128;

    float acc[8][8];
#pragma unroll
    for (int i=0;i<8;i++)
#pragma unroll
        for (int j=0;j<8;j++) acc[i][j]=0.f;

    const int arow = tid >> 1, acol = (tid & 1)*4;
    const int brow = tid >> 5, bcol = (tid & 31)*4;
    const float* Ap = g_O + (size_t)(m0+arow)*KD + acol;
    const float* Bp = W   + (size_t)brow*N + n0 + bcol;

    for (int kt=0; kt<KD; kt+=8){
        float4 av = *(const float4*)(Ap + kt);
        float4 bv = *(const float4*)(Bp + (size_t)kt*N);
        As[(acol+0)*132+arow]=av.x;
        As[(acol+1)*132+arow]=av.y;
        As[(acol+2)*132+arow]=av.z;
        As[(acol+3)*132+arow]=av.w;
        *(float4*)&Bs[brow*132+bcol]=bv;
        __syncthreads();
#pragma unroll
        for (int k=0;k<8;k++){
            float4 a0=*(float4*)&As[k*132+ty*4];
            float4 a1=*(float4*)&As[k*132+64+ty*4];
            float4 b0=*(float4*)&Bs[k*132+tx*4];
            float4 b1=*(float4*)&Bs[k*132+64+tx*4];
            float ar[8]={a0.x,a0.y,a0.z,a0.w,a1.x,a1.y,a1.z,a1.w};
            float br[8]={b0.x,b0.y,b0.z,b0.w,b1.x,b1.y,b1.z,b1.w};
#pragma unroll
            for (int i=0;i<8;i++)
#pragma unroll
                for (int j=0;j<8;j++) acc[i][j]=fmaf(ar[i],br[j],acc[i][j]);
        }
        __syncthreads();
    }

#pragma unroll
    for (int gj=0; gj<2; gj++){
        const int n = n0 + gj*64 + tx*4;
        const float4 bs4 = *(const float4*)&bias[n];
#pragma unroll
        for (int gi=0; gi<2; gi++){
            const int row0 = m0 + gi*64 + ty*4;
#pragma unroll
            for (int ii=0; ii<4; ii++){
                float4 v;
                v.x = acc[gi*4+ii][gj*4+0] + bs4.x;
                v.y = acc[gi*4+ii][gj*4+1] + bs4.y;
                v.z = acc[gi*4+ii][gj*4+2] + bs4.z;
                v.w = acc[gi*4+ii][gj*4+3] + bs4.w;
                *(float4*)&out[(size_t)(row0+ii)*N + n] = v;
            }
        }
    }
}

// ---------------------------------------------------------------------------
extern "C" void kernel_launch(void* const* d_in, const int* in_sizes, int n_in,
                              void* d_out, int out_size)
{
    const float* x     = (const float*)d_in[0];
    const int*   mask  = (const int*)  d_in[1];
    const float* w_qkv = (const float*)d_in[2];
    const float* b_qkv = (const float*)d_in[3];
    const float* w_out = (const float*)d_in[4];
    const float* b_out = (const float*)d_in[5];
    float* out = (float*)d_out;

    cudaFuncSetAttribute(attn_kernel, cudaFuncAttributeMaxDynamicSharedMemorySize, 69632);

    qkv_gemm <<<dim3(3*EMBED/128, MROWS/128), 256>>>(x, w_qkv, b_qkv);
    attn_kernel<<<dim3(SEQ/64, NHEADS, BATCH), 256, 69632>>>(mask);
    out_gemm <<<dim3(EMBED/128, MROWS/128), 256>>>(w_out, b_out, out);
}

// round 3
// speedup vs baseline: 1.1959x; 1.1959x over previous
#include <cuda_runtime.h>
#include <mma.h>
using namespace nvcuda;

#define EMBED  1024
#define NHEADS 16
#define HDIM   64
#define BATCH  4
#define SEQ    2048
#define MROWS  (BATCH*SEQ)   /* 8192 */

// Scratch (static __device__, no allocation)
__device__ float g_Q [BATCH*NHEADS*SEQ*HDIM];   // (b,h,s,d)
__device__ float g_Kt[BATCH*NHEADS*HDIM*SEQ];   // (b,h,d,s)  -- transposed K
__device__ float g_V [BATCH*NHEADS*SEQ*HDIM];   // (b,h,s,d)
__device__ float g_O [BATCH*SEQ*EMBED];         // (b,s,e)

__device__ __forceinline__ float ex2a(float x){
    float y; asm("ex2.approx.f32 %0, %1;" : "=f"(y) : "f"(x)); return y;
}
__device__ __forceinline__ float t32(float x){ return wmma::__float_to_tf32(x); }

// ---------------------------------------------------------------------------
// Shared GEMM body: C(128x128) = A(128xK) @ B(Kx128), tf32 wmma m16n16k8.
// 256 threads = 8 warps as 2(M) x 4(N); warp tile 64x32 = 4x2 fragments.
// As[128][36], Bs[32][132], C overlay Cs[128][132].
// ---------------------------------------------------------------------------
#define AS_STRIDE 36
#define BS_STRIDE 132
#define CS_STRIDE 132

// ---------------------------------------------------------------------------
// QKV GEMM: (8192x1024)@(1024x3072)+bias -> scatter Q / Kt / V
// ---------------------------------------------------------------------------
__global__ __launch_bounds__(256) void qkv_gemm(const float* __restrict__ X,
                                                const float* __restrict__ W,
                                                const float* __restrict__ bias)
{
    extern __shared__ float sm[];
    float* As = sm;                    // [128][36]
    float* Bs = sm + 128*AS_STRIDE;    // [32][132]
    float* Cs = sm;                    // overlay [128][132]

    const int tid = threadIdx.x, wid = tid >> 5;
    const int wm = wid & 1, wn = wid >> 1;
    const int m0 = blockIdx.y * 128;
    const int n0 = blockIdx.x * 128;
    const int N  = 3*EMBED;

    wmma::fragment<wmma::accumulator,16,16,8,float> acc[4][2];
#pragma unroll
    for (int i=0;i<4;i++)
#pragma unroll
        for (int f=0;f<2;f++) wmma::fill_fragment(acc[i][f], 0.0f);

    for (int kt=0; kt<EMBED; kt+=32){
#pragma unroll
        for (int j=0;j<4;j++){                       // A: 128x32
            int idx = tid + j*256;
            int r = idx >> 3, c4 = (idx & 7)*4;
            float4 v = *(const float4*)&X[(size_t)(m0+r)*EMBED + kt + c4];
            As[r*AS_STRIDE+c4+0]=t32(v.x); As[r*AS_STRIDE+c4+1]=t32(v.y);
            As[r*AS_STRIDE+c4+2]=t32(v.z); As[r*AS_STRIDE+c4+3]=t32(v.w);
        }
#pragma unroll
        for (int j=0;j<4;j++){                       // B: 32x128
            int idx = tid + j*256;
            int r = idx >> 5, c4 = (idx & 31)*4;
            float4 v = *(const float4*)&W[(size_t)(kt+r)*N + n0 + c4];
            Bs[r*BS_STRIDE+c4+0]=t32(v.x); Bs[r*BS_STRIDE+c4+1]=t32(v.y);
            Bs[r*BS_STRIDE+c4+2]=t32(v.z); Bs[r*BS_STRIDE+c4+3]=t32(v.w);
        }
        __syncthreads();
#pragma unroll
        for (int k8=0;k8<32;k8+=8){
            wmma::fragment<wmma::matrix_a,16,16,8,wmma::precision::tf32,wmma::row_major> af[4];
            wmma::fragment<wmma::matrix_b,16,16,8,wmma::precision::tf32,wmma::row_major> bf[2];
#pragma unroll
            for (int i=0;i<4;i++)
                wmma::load_matrix_sync(af[i], &As[(wm*64+i*16)*AS_STRIDE + k8], AS_STRIDE);
#pragma unroll
            for (int f=0;f<2;f++)
                wmma::load_matrix_sync(bf[f], &Bs[k8*BS_STRIDE + wn*32 + f*16], BS_STRIDE);
#pragma unroll
            for (int i=0;i<4;i++)
#pragma unroll
                for (int f=0;f<2;f++)
                    wmma::mma_sync(acc[i][f], af[i], bf[f], acc[i][f]);
        }
        __syncthreads();
    }

#pragma unroll
    for (int i=0;i<4;i++)
#pragma unroll
        for (int f=0;f<2;f++)
            wmma::store_matrix_sync(&Cs[(wm*64+i*16)*CS_STRIDE + wn*32 + f*16],
                                    acc[i][f], CS_STRIDE, wmma::mem_row_major);
    __syncthreads();

    // Scatter epilogue. n-tile lies entirely in one of {Q,K,V} (boundaries mult of 128).
    const int three = n0 >> 10;
    if (three == 1){
        // K transposed: g_Kt[(bh*64+d)*SEQ + s]
        for (int u = tid; u < 128*128; u += 256){
            int c = u >> 7, s = u & 127;
            int n = n0 + c;
            int h = (n & 1023) >> 6, d = n & 63;
            int row = m0 + s;
            int bb = row >> 11, s0 = row & 2047;
            g_Kt[((size_t)(bb*NHEADS + h)*HDIM + d)*SEQ + s0] = Cs[s*CS_STRIDE + c] + bias[n];
        }
    } else {
        float* dst = (three == 0) ? g_Q : g_V;
#pragma unroll
        for (int j=0;j<16;j++){
            int idx = tid + j*256;
            int r = idx >> 5, c4 = (idx & 31)*4;
            int n = n0 + c4;
            int h = (n & 1023) >> 6, d = n & 63;
            int row = m0 + r;
            int bb = row >> 11, s0 = row & 2047;
            float4 b4 = *(const float4*)&bias[n];
            float4 v;
            v.x = Cs[r*CS_STRIDE+c4+0] + b4.x;
            v.y = Cs[r*CS_STRIDE+c4+1] + b4.y;
            v.z = Cs[r*CS_STRIDE+c4+2] + b4.z;
            v.w = Cs[r*CS_STRIDE+c4+3] + b4.w;
            *(float4*)&dst[((size_t)(bb*NHEADS + h)*SEQ + s0)*HDIM + d] = v;
        }
    }
}

// ---------------------------------------------------------------------------
// Flash attention, wmma tf32 for S = Q K^T and O += P V.
// 256 thr = 8 warps as 4(M) x 2(N); warp tile 16x32 for both GEMMs.
// Softmax / O-accum: fixed mapping row = tid>>2, cols (tid&3)*16 .. +15.
// smem: Qs[64][68], Ks[64][68] (reused as PV result), Vs[64][68], Ss[64][68]
// ---------------------------------------------------------------------------
#define TS 68
__global__ __launch_bounds__(256) void attn_kernel(const int* __restrict__ mask)
{
    extern __shared__ float sm[];
    float* Qs = sm;
    float* Ks = sm + 64*TS;      // also PV-result staging
    float* Vs = sm + 2*64*TS;
    float* Ss = sm + 3*64*TS;    // S, then P (tf32)

    const int qb = blockIdx.x, h = blockIdx.y, bb = blockIdx.z;
    const int tid = threadIdx.x, wid = tid >> 5;
    const int wm = wid & 3, wn = wid >> 2;
    const int trow = tid >> 2, tseg = tid & 3;

    const float* Qg = g_Q  + ((size_t)(bb*NHEADS + h)*SEQ + qb*64)*HDIM;
    const float* Kg = g_Kt +  (size_t)(bb*NHEADS + h)*HDIM*SEQ;
    const float* Vg = g_V  +  (size_t)(bb*NHEADS + h)*SEQ*HDIM;
    const int*   Mg = mask +  ((size_t)bb*SEQ + qb*64)*SEQ;

#pragma unroll
    for (int j=0;j<4;j++){                 // Q tile, tf32
        int idx = tid + j*256;
        int r = idx >> 4, c4 = (idx & 15)*4;
        float4 v = *(const float4*)&Qg[r*HDIM + c4];
        Qs[r*TS+c4+0]=t32(v.x); Qs[r*TS+c4+1]=t32(v.y);
        Qs[r*TS+c4+2]=t32(v.z); Qs[r*TS+c4+3]=t32(v.w);
    }

    float o[16];
#pragma unroll
    for (int j=0;j<16;j++) o[j]=0.f;
    float m_i = -1e30f, l_i = 0.f;
    const float CE = 0.18033688011112042f;   // log2(e)/sqrt(64)

    for (int kt = 0; kt < SEQ/64; kt++){
        const int k0 = kt*64;
        __syncthreads();                     // prior iter readers of Ks/Vs done
#pragma unroll
        for (int j=0;j<4;j++){
            int idx = tid + j*256;
            int r = idx >> 4, c4 = (idx & 15)*4;
            float4 kv = *(const float4*)&Kg[(size_t)r*SEQ + k0 + c4];
            Ks[r*TS+c4+0]=t32(kv.x); Ks[r*TS+c4+1]=t32(kv.y);
            Ks[r*TS+c4+2]=t32(kv.z); Ks[r*TS+c4+3]=t32(kv.w);
            float4 vv = *(const float4*)&Vg[(size_t)(k0+r)*HDIM + c4];
            Vs[r*TS+c4+0]=t32(vv.x); Vs[r*TS+c4+1]=t32(vv.y);
            Vs[r*TS+c4+2]=t32(vv.z); Vs[r*TS+c4+3]=t32(vv.w);
        }
        __syncthreads();

        // S = Q @ K^T  (Ks is d-major: row = d, col = key -> row-major B)
        {
            wmma::fragment<wmma::accumulator,16,16,8,float> sacc[2];
            wmma::fill_fragment(sacc[0], 0.f);
            wmma::fill_fragment(sacc[1], 0.f);
#pragma unroll
            for (int k8=0;k8<64;k8+=8){
                wmma::fragment<wmma::matrix_a,16,16,8,wmma::precision::tf32,wmma::row_major> af;
                wmma::fragment<wmma::matrix_b,16,16,8,wmma::precision::tf32,wmma::row_major> bf[2];
                wmma::load_matrix_sync(af, &Qs[(wm*16)*TS + k8], TS);
                wmma::load_matrix_sync(bf[0], &Ks[k8*TS + wn*32 +  0], TS);
                wmma::load_matrix_sync(bf[1], &Ks[k8*TS + wn*32 + 16], TS);
                wmma::mma_sync(sacc[0], af, bf[0], sacc[0]);
                wmma::mma_sync(sacc[1], af, bf[1], sacc[1]);
            }
            wmma::store_matrix_sync(&Ss[(wm*16)*TS + wn*32 +  0], sacc[0], TS, wmma::mem_row_major);
            wmma::store_matrix_sync(&Ss[(wm*16)*TS + wn*32 + 16], sacc[1], TS, wmma::mem_row_major);
        }
        __syncthreads();

        // online softmax on row trow, cols tseg*16..+15
        {
            float s[16];
            const int*  mrow = Mg + (size_t)trow*SEQ + k0 + tseg*16;
            float* srow = &Ss[trow*TS + tseg*16];
#pragma unroll
            for (int j4=0;j4<4;j4++){
                float4 sv = *(const float4*)&srow[j4*4];
                int4   mv = *(const int4*)&mrow[j4*4];
                s[j4*4+0] = mv.x ? sv.x : -1e30f;
                s[j4*4+1] = mv.y ? sv.y : -1e30f;
                s[j4*4+2] = mv.z ? sv.z : -1e30f;
                s[j4*4+3] = mv.w ? sv.w : -1e30f;
            }
            float rm = s[0];
#pragma unroll
            for (int j=1;j<16;j++) rm = fmaxf(rm, s[j]);
            rm = fmaxf(rm, __shfl_xor_sync(0xffffffffu, rm, 1));
            rm = fmaxf(rm, __shfl_xor_sync(0xffffffffu, rm, 2));
            const float mn = fmaxf(m_i, rm);
            const float alpha = ex2a((m_i - mn)*CE);
            m_i = mn;
            float rs = 0.f;
#pragma unroll
            for (int j=0;j<16;j++){
                float p = ex2a((s[j] - mn)*CE);
                rs += p;
                srow[j] = t32(p);
            }
            rs += __shfl_xor_sync(0xffffffffu, rs, 1);
            rs += __shfl_xor_sync(0xffffffffu, rs, 2);
            l_i = l_i*alpha + rs;
#pragma unroll
            for (int j=0;j<16;j++) o[j] *= alpha;
        }
        __syncthreads();

        // PV = P @ V  (A = Ss row-major over keys, B = Vs row-major key x d)
        {
            wmma::fragment<wmma::accumulator,16,16,8,float> pacc[2];
            wmma::fill_fragment(pacc[0], 0.f);
            wmma::fill_fragment(pacc[1], 0.f);
#pragma unroll
            for (int k8=0;k8<64;k8+=8){
                wmma::fragment<wmma::matrix_a,16,16,8,wmma::precision::tf32,wmma::row_major> af;
                wmma::fragment<wmma::matrix_b,16,16,8,wmma::precision::tf32,wmma::row_major> bf[2];
                wmma::load_matrix_sync(af, &Ss[(wm*16)*TS + k8], TS);
                wmma::load_matrix_sync(bf[0], &Vs[k8*TS + wn*32 +  0], TS);
                wmma::load_matrix_sync(bf[1], &Vs[k8*TS + wn*32 + 16], TS);
                wmma::mma_sync(pacc[0], af, bf[0], pacc[0]);
                wmma::mma_sync(pacc[1], af, bf[1], pacc[1]);
            }
            wmma::store_matrix_sync(&Ks[(wm*16)*TS + wn*32 +  0], pacc[0], TS, wmma::mem_row_major);
            wmma::store_matrix_sync(&Ks[(wm*16)*TS + wn*32 + 16], pacc[1], TS, wmma::mem_row_major);
        }
        __syncthreads();

        // O accumulate (alpha already applied above)
        {
            const float* pv = &Ks[trow*TS + tseg*16];
#pragma unroll
            for (int j=0;j<16;j++) o[j] += pv[j];
        }
    }

    // writeout: g_O (b,s,e) with e = h*64 + d
    const float inv = 1.0f / l_i;
    const int qrow = qb*64 + trow;
    float* dst = &g_O[((size_t)bb*SEQ + qrow)*EMBED + h*HDIM + tseg*16];
#pragma unroll
    for (int j4=0;j4<4;j4++){
        float4 v = make_float4(o[j4*4+0]*inv, o[j4*4+1]*inv, o[j4*4+2]*inv, o[j4*4+3]*inv);
        *(float4*)&dst[j4*4] = v;
    }
}

// ---------------------------------------------------------------------------
// Output projection: (8192x1024)@(1024x1024)+bias -> d_out
// ---------------------------------------------------------------------------
__global__ __launch_bounds__(256) void out_gemm(const float* __restrict__ W,
                                                const float* __restrict__ bias,
                                                float* __restrict__ out)
{
    extern __shared__ float sm[];
    float* As = sm;
    float* Bs = sm + 128*AS_STRIDE;
    float* Cs = sm;

    const int tid = threadIdx.x, wid = tid >> 5;
    const int wm = wid & 1, wn = wid >> 1;
    const int m0 = blockIdx.y * 128;
    const int n0 = blockIdx.x * 128;
    const int N  = EMBED;

    wmma::fragment<wmma::accumulator,16,16,8,float> acc[4][2];
#pragma unroll
    for (int i=0;i<4;i++)
#pragma unroll
        for (int f=0;f<2;f++) wmma::fill_fragment(acc[i][f], 0.0f);

    for (int kt=0; kt<EMBED; kt+=32){
#pragma unroll
        for (int j=0;j<4;j++){
            int idx = tid + j*256;
            int r = idx >> 3, c4 = (idx & 7)*4;
            float4 v = *(const float4*)&g_O[(size_t)(m0+r)*EMBED + kt + c4];
            As[r*AS_STRIDE+c4+0]=t32(v.x); As[r*AS_STRIDE+c4+1]=t32(v.y);
            As[r*AS_STRIDE+c4+2]=t32(v.z); As[r*AS_STRIDE+c4+3]=t32(v.w);
        }
#pragma unroll
        for (int j=0;j<4;j++){
            int idx = tid + j*256;
            int r = idx >> 5, c4 = (idx & 31)*4;
            float4 v = *(const float4*)&W[(size_t)(kt+r)*N + n0 + c4];
            Bs[r*BS_STRIDE+c4+0]=t32(v.x); Bs[r*BS_STRIDE+c4+1]=t32(v.y);
            Bs[r*BS_STRIDE+c4+2]=t32(v.z); Bs[r*BS_STRIDE+c4+3]=t32(v.w);
        }
        __syncthreads();
#pragma unroll
        for (int k8=0;k8<32;k8+=8){
            wmma::fragment<wmma::matrix_a,16,16,8,wmma::precision::tf32,wmma::row_major> af[4];
            wmma::fragment<wmma::matrix_b,16,16,8,wmma::precision::tf32,wmma::row_major> bf[2];
#pragma unroll
            for (int i=0;i<4;i++)
                wmma::load_matrix_sync(af[i], &As[(wm*64+i*16)*AS_STRIDE + k8], AS_STRIDE);
#pragma unroll
            for (int f=0;f<2;f++)
                wmma::load_matrix_sync(bf[f], &Bs[k8*BS_STRIDE + wn*32 + f*16], BS_STRIDE);
#pragma unroll
            for (int i=0;i<4;i++)
#pragma unroll
                for (int f=0;f<2;f++)
                    wmma::mma_sync(acc[i][f], af[i], bf[f], acc[i][f]);
        }
        __syncthreads();
    }

#pragma unroll
    for (int i=0;i<4;i++)
#pragma unroll
        for (int f=0;f<2;f++)
            wmma::store_matrix_sync(&Cs[(wm*64+i*16)*CS_STRIDE + wn*32 + f*16],
                                    acc[i][f], CS_STRIDE, wmma::mem_row_major);
    __syncthreads();

#pragma unroll
    for (int j=0;j<16;j++){
        int idx = tid + j*256;
        int r = idx >> 5, c4 = (idx & 31)*4;
        float4 b4 = *(const float4*)&bias[n0 + c4];
        float4 v;
        v.x = Cs[r*CS_STRIDE+c4+0] + b4.x;
        v.y = Cs[r*CS_STRIDE+c4+1] + b4.y;
        v.z = Cs[r*CS_STRIDE+c4+2] + b4.z;
        v.w = Cs[r*CS_STRIDE+c4+3] + b4.w;
        *(float4*)&out[(size_t)(m0+r)*N + n0 + c4] = v;
    }
}

// ---------------------------------------------------------------------------
extern "C" void kernel_launch(void* const* d_in, const int* in_sizes, int n_in,
                              void* d_out, int out_size)
{
    const float* x     = (const float*)d_in[0];
    const int*   mask  = (const int*)  d_in[1];
    const float* w_qkv = (const float*)d_in[2];
    const float* b_qkv = (const float*)d_in[3];
    const float* w_out = (const float*)d_in[4];
    const float* b_out = (const float*)d_in[5];
    float* out = (float*)d_out;

    const int gemm_smem = 128*132*sizeof(float);          // 67584 (C overlay)
    const int attn_smem = 4*64*TS*sizeof(float);          // 69632

    cudaFuncSetAttribute(qkv_gemm,   cudaFuncAttributeMaxDynamicSharedMemorySize, gemm_smem);
    cudaFuncSetAttribute(attn_kernel,cudaFuncAttributeMaxDynamicSharedMemorySize, attn_smem);
    cudaFuncSetAttribute(out_gemm,   cudaFuncAttributeMaxDynamicSharedMemorySize, gemm_smem);

    qkv_gemm   <<<dim3(3*EMBED/128, MROWS/128), 256, gemm_smem>>>(x, w_qkv, b_qkv);
    attn_kernel<<<dim3(SEQ/64, NHEADS, BATCH), 256, attn_smem>>>(mask);
    out_gemm   <<<dim3(EMBED/128, MROWS/128), 256, gemm_smem>>>(w_out, b_out, out);
}

// round 9
// speedup vs baseline: 1.2322x; 1.0303x over previous
#include <cuda_runtime.h>
#include <mma.h>
#include <cstdint>
using namespace nvcuda;

#define EMBED  1024
#define NHEADS 16
#define HDIM   64
#define BATCH  4
#define SEQ    2048
#define MROWS  (BATCH*SEQ)   /* 8192 */

// Scratch (static __device__, no allocation)
__device__ float g_Q [BATCH*NHEADS*SEQ*HDIM];   // (b,h,s,d)
__device__ float g_Kt[BATCH*NHEADS*HDIM*SEQ];   // (b,h,d,s)  -- transposed K
__device__ float g_V [BATCH*NHEADS*SEQ*HDIM];   // (b,h,s,d)
__device__ float g_O [BATCH*SEQ*EMBED];         // (b,s,e)

__device__ __forceinline__ float ex2a(float x){
    float y; asm("ex2.approx.f32 %0, %1;" : "=f"(y) : "f"(x)); return y;
}
__device__ __forceinline__ uint32_t smem_u32(const void* p){
    uint32_t a;
    asm("{ .reg .u64 t; cvta.to.shared.u64 t, %1; cvt.u32.u64 %0, t; }" : "=r"(a) : "l"(p));
    return a;
}
__device__ __forceinline__ void cpa16(uint32_t dst, const void* src){
    asm volatile("cp.async.cg.shared.global [%0], [%1], 16;" :: "r"(dst), "l"(src));
}
#define CPA_COMMIT()  asm volatile("cp.async.commit_group;" ::: "memory")
#define CPA_WAIT(N)   asm volatile("cp.async.wait_group %0;" :: "n"(N) : "memory")

// RN fp32 -> tf32 on fragment elements (the documented tf32-wmma pattern).
// Raw fp32 reaches smem via cp.async; HMMA would otherwise TRUNCATE (biased).
template<class Frag>
__device__ __forceinline__ void cvt_frag(Frag& f){
#pragma unroll
    for (int t = 0; t < f.num_elements; t++)
        f.x[t] = wmma::__float_to_tf32(f.x[t]);
}

// ===========================================================================
// Projection GEMM: C[128,128] tile of A[M,1024] @ W[1024,Nw] (+bias via MMA).
// BK=16 double-buffered cp.async; direct gmem epilogue. mode 0=QKV, 1=out.
// smem (floats): As0 0, As1 2560, Bs0 5120, Bs1 7232, OnesA 9344, BiasB 9472
// ===========================================================================
#define PA(buf)   ((buf)*2560)
#define PB(buf)   (5120 + (buf)*2112)
#define P_ONE     9344
#define P_BIAS    9472
#define PROJ_SMEM (10528*4)

__global__ __launch_bounds__(256,2) void proj_gemm(
    const float* __restrict__ Ag_in, const float* __restrict__ Wg,
    const float* __restrict__ bias,  float* __restrict__ outp,
    int Nw, int mode)
{
    extern __shared__ float smf[];
    const uint32_t sb = smem_u32(smf);
    const int tid = threadIdx.x, wid = tid >> 5;
    const int wm = wid & 1, wn = wid >> 1;
    const int n0 = blockIdx.x * 128, m0 = blockIdx.y * 128;
    const float* Ag = Ag_in ? Ag_in : g_O;

    // issue chunk 0 stage immediately
    {
        int r = tid >> 2, c4 = (tid & 3)*4;
        cpa16(sb + (PA(0) + r*20 + c4)*4,        &Ag[(size_t)(m0+r)*EMBED + c4]);
        int r2 = (tid+256) >> 2, c42 = ((tid+256) & 3)*4;
        cpa16(sb + (PA(0) + r2*20 + c42)*4,      &Ag[(size_t)(m0+r2)*EMBED + c42]);
        int br = tid >> 5, bc = (tid & 31)*4;
        cpa16(sb + (PB(0) + br*132 + bc)*4,      &Wg[(size_t)br*Nw + n0 + bc]);
        int br2 = (tid+256) >> 5, bc2 = ((tid+256) & 31)*4;
        cpa16(sb + (PB(0) + br2*132 + bc2)*4,    &Wg[(size_t)br2*Nw + n0 + bc2]);
    }
    CPA_COMMIT();

    // stage ones/bias matrices (plain stores)
    if (tid < 128) smf[P_ONE + tid] = ((tid & 7) == 0) ? 1.0f : 0.0f;
    for (int idx = tid; idx < 1056; idx += 256){
        int r = idx / 132, c = idx % 132;
        smf[P_BIAS + idx] = (r == 0 && c < 128) ? bias[n0 + c] : 0.0f;
    }
    __syncthreads();

    // acc[i][f] initialized to bias row via ones-column MMA
    wmma::fragment<wmma::accumulator,16,16,8,float> acc[4][2];
    {
        wmma::fragment<wmma::matrix_a,16,16,8,wmma::precision::tf32,wmma::row_major> a1;
        wmma::fragment<wmma::matrix_b,16,16,8,wmma::precision::tf32,wmma::row_major> bb[2];
        wmma::load_matrix_sync(a1, &smf[P_ONE], 8);
        wmma::load_matrix_sync(bb[0], &smf[P_BIAS + wn*32 +  0], 132);
        wmma::load_matrix_sync(bb[1], &smf[P_BIAS + wn*32 + 16], 132);
        cvt_frag(a1); cvt_frag(bb[0]); cvt_frag(bb[1]);
#pragma unroll
        for (int i=0;i<4;i++)
#pragma unroll
            for (int f=0;f<2;f++){
                wmma::fill_fragment(acc[i][f], 0.0f);
                wmma::mma_sync(acc[i][f], a1, bb[f], acc[i][f]);
            }
    }

    for (int c = 0; c < 64; c++){
        const int buf = c & 1;
        if (c < 63){
            const int kt = (c+1)*16, nb = buf ^ 1;
            int r = tid >> 2, c4 = (tid & 3)*4;
            cpa16(sb + (PA(nb) + r*20 + c4)*4,     &Ag[(size_t)(m0+r)*EMBED + kt + c4]);
            int r2 = (tid+256) >> 2, c42 = ((tid+256) & 3)*4;
            cpa16(sb + (PA(nb) + r2*20 + c42)*4,   &Ag[(size_t)(m0+r2)*EMBED + kt + c42]);
            int br = tid >> 5, bc = (tid & 31)*4;
            cpa16(sb + (PB(nb) + br*132 + bc)*4,   &Wg[(size_t)(kt+br)*Nw + n0 + bc]);
            int br2 = (tid+256) >> 5, bc2 = ((tid+256) & 31)*4;
            cpa16(sb + (PB(nb) + br2*132 + bc2)*4, &Wg[(size_t)(kt+br2)*Nw + n0 + bc2]);
            CPA_COMMIT();
            CPA_WAIT(1);
        } else {
            CPA_WAIT(0);
        }
        __syncthreads();

        const float* As = &smf[PA(buf)];
        const float* Bs = &smf[PB(buf)];
#pragma unroll
        for (int k8=0;k8<16;k8+=8){
            wmma::fragment<wmma::matrix_a,16,16,8,wmma::precision::tf32,wmma::row_major> af[4];
            wmma::fragment<wmma::matrix_b,16,16,8,wmma::precision::tf32,wmma::row_major> bf[2];
#pragma unroll
            for (int i=0;i<4;i++){
                wmma::load_matrix_sync(af[i], &As[(wm*64+i*16)*20 + k8], 20);
                cvt_frag(af[i]);
            }
#pragma unroll
            for (int f=0;f<2;f++){
                wmma::load_matrix_sync(bf[f], &Bs[k8*132 + wn*32 + f*16], 132);
                cvt_frag(bf[f]);
            }
#pragma unroll
            for (int i=0;i<4;i++)
#pragma unroll
                for (int f=0;f<2;f++)
                    wmma::mma_sync(acc[i][f], af[i], bf[f], acc[i][f]);
        }
        __syncthreads();
    }

    // direct-to-gmem epilogue
#pragma unroll
    for (int f=0; f<2; f++){
        const int nc = n0 + wn*32 + f*16;
#pragma unroll
        for (int i=0; i<4; i++){
            const int mr = m0 + wm*64 + i*16;
            if (mode == 1){
                wmma::store_matrix_sync(&outp[(size_t)mr*EMBED + nc], acc[i][f],
                                        EMBED, wmma::mem_row_major);
            } else {
                const int three = n0 >> 10;
                const int h  = (nc & 1023) >> 6, d0 = nc & 63;
                const int bb = mr >> 11, s0 = mr & 2047;
                if (three == 1){
                    wmma::store_matrix_sync(
                        &g_Kt[((size_t)(bb*NHEADS + h)*HDIM + d0)*SEQ + s0],
                        acc[i][f], SEQ, wmma::mem_col_major);
                } else {
                    float* dst = three ? g_V : g_Q;
                    wmma::store_matrix_sync(
                        &dst[((size_t)(bb*NHEADS + h)*SEQ + s0)*HDIM + d0],
                        acc[i][f], HDIM, wmma::mem_row_major);
                }
            }
        }
    }
}

// ===========================================================================
// Flash attention, wmma tf32 + cp.async prefetch.
// smem (floats): Qs 0, Ks 4352, Vs0 8704, Vs1 13056, Ss 17408, Os 21760
// ===========================================================================
#define ATT_QS 0
#define ATT_KS 4352
#define ATT_VS(b) (8704 + (b)*4352)
#define ATT_SS 17408
#define ATT_OS 21760
#define ATT_SMEM (26112*4)
#define TS 68

__global__ __launch_bounds__(256,2) void attn_kernel(const int* __restrict__ mask)
{
    extern __shared__ float smf[];
    const uint32_t sb = smem_u32(smf);

    const int qb = blockIdx.x, h = blockIdx.y, bb = blockIdx.z;
    const int tid = threadIdx.x, wid = tid >> 5;
    const int wm = wid & 3, wn = wid >> 2;
    const int trow = tid >> 2, tseg = tid & 3;

    const float* Qg = g_Q  + ((size_t)(bb*NHEADS + h)*SEQ + qb*64)*HDIM;
    const float* Kg = g_Kt +  (size_t)(bb*NHEADS + h)*HDIM*SEQ;
    const float* Vg = g_V  +  (size_t)(bb*NHEADS + h)*SEQ*HDIM;
    const int*   Mg = mask +  ((size_t)bb*SEQ + qb*64)*SEQ;

    // prologue: stage Q, K0, V0
#pragma unroll
    for (int j=0;j<4;j++){
        int idx = tid + j*256;
        int r = idx >> 4, c4 = (idx & 15)*4;
        cpa16(sb + (ATT_QS    + r*TS + c4)*4, &Qg[r*HDIM + c4]);
        cpa16(sb + (ATT_KS    + r*TS + c4)*4, &Kg[(size_t)r*SEQ + c4]);
        cpa16(sb + (ATT_VS(0) + r*TS + c4)*4, &Vg[(size_t)r*HDIM + c4]);
    }
    CPA_COMMIT();
    CPA_WAIT(0);
    __syncthreads();

    float o[16];
#pragma unroll
    for (int j=0;j<16;j++) o[j]=0.f;
    float m_i = -1e30f, l_i = 0.f;
    const float CE = 0.18033688011112042f;   // log2(e)/sqrt(64)

    for (int kt = 0; kt < SEQ/64; kt++){
        const int buf = kt & 1;
        const int k0 = kt*64;

        // S = Q @ K^T (Ks is d-major: row=d, col=key)
        {
            wmma::fragment<wmma::accumulator,16,16,8,float> sacc[2];
            wmma::fill_fragment(sacc[0], 0.f);
            wmma::fill_fragment(sacc[1], 0.f);
#pragma unroll
            for (int k8=0;k8<64;k8+=8){
                wmma::fragment<wmma::matrix_a,16,16,8,wmma::precision::tf32,wmma::row_major> af;
                wmma::fragment<wmma::matrix_b,16,16,8,wmma::precision::tf32,wmma::row_major> bf[2];
                wmma::load_matrix_sync(af, &smf[ATT_QS + (wm*16)*TS + k8], TS);
                wmma::load_matrix_sync(bf[0], &smf[ATT_KS + k8*TS + wn*32 +  0], TS);
                wmma::load_matrix_sync(bf[1], &smf[ATT_KS + k8*TS + wn*32 + 16], TS);
                cvt_frag(af); cvt_frag(bf[0]); cvt_frag(bf[1]);
                wmma::mma_sync(sacc[0], af, bf[0], sacc[0]);
                wmma::mma_sync(sacc[1], af, bf[1], sacc[1]);
            }
            wmma::store_matrix_sync(&smf[ATT_SS + (wm*16)*TS + wn*32 +  0], sacc[0], TS, wmma::mem_row_major);
            wmma::store_matrix_sync(&smf[ATT_SS + (wm*16)*TS + wn*32 + 16], sacc[1], TS, wmma::mem_row_major);
        }
        __syncthreads();                                  // [1] S visible; Ks free

        // prefetch next K and next V (into alternate V buffer)
        if (kt + 1 < SEQ/64){
            const int kn = k0 + 64;
#pragma unroll
            for (int j=0;j<4;j++){
                int idx = tid + j*256;
                int r = idx >> 4, c4 = (idx & 15)*4;
                cpa16(sb + (ATT_KS + r*TS + c4)*4,        &Kg[(size_t)r*SEQ + kn + c4]);
                cpa16(sb + (ATT_VS(buf^1) + r*TS + c4)*4, &Vg[(size_t)(kn+r)*HDIM + c4]);
            }
            CPA_COMMIT();
        }

        // online softmax on row trow, cols tseg*16..+15 (in place in Ss)
        {
            float s[16];
            const int* mrow = Mg + (size_t)trow*SEQ + k0 + tseg*16;
            float* srow = &smf[ATT_SS + trow*TS + tseg*16];
#pragma unroll
            for (int j4=0;j4<4;j4++){
                float4 sv = *(const float4*)&srow[j4*4];
                int4   mv = *(const int4*)&mrow[j4*4];
                s[j4*4+0] = mv.x ? sv.x : -1e30f;
                s[j4*4+1] = mv.y ? sv.y : -1e30f;
                s[j4*4+2] = mv.z ? sv.z : -1e30f;
                s[j4*4+3] = mv.w ? sv.w : -1e30f;
            }
            float rm = s[0];
#pragma unroll
            for (int j=1;j<16;j++) rm = fmaxf(rm, s[j]);
            rm = fmaxf(rm, __shfl_xor_sync(0xffffffffu, rm, 1));
            rm = fmaxf(rm, __shfl_xor_sync(0xffffffffu, rm, 2));
            const float mn = fmaxf(m_i, rm);
            const float alpha = ex2a((m_i - mn)*CE);
            m_i = mn;
            float rs = 0.f;
#pragma unroll
            for (int j=0;j<16;j++){
                float p = ex2a((s[j] - mn)*CE);
                rs += p;
                srow[j] = p;
            }
            rs += __shfl_xor_sync(0xffffffffu, rs, 1);
            rs += __shfl_xor_sync(0xffffffffu, rs, 2);
            l_i = l_i*alpha + rs;
#pragma unroll
            for (int j=0;j<16;j++) o[j] *= alpha;
        }
        __syncthreads();                                  // [2] P visible

        // PV = P @ V -> Os
        {
            wmma::fragment<wmma::accumulator,16,16,8,float> pacc[2];
            wmma::fill_fragment(pacc[0], 0.f);
            wmma::fill_fragment(pacc[1], 0.f);
#pragma unroll
            for (int k8=0;k8<64;k8+=8){
                wmma::fragment<wmma::matrix_a,16,16,8,wmma::precision::tf32,wmma::row_major> af;
                wmma::fragment<wmma::matrix_b,16,16,8,wmma::precision::tf32,wmma::row_major> bf[2];
                wmma::load_matrix_sync(af, &smf[ATT_SS + (wm*16)*TS + k8], TS);
                wmma::load_matrix_sync(bf[0], &smf[ATT_VS(buf) + k8*TS + wn*32 +  0], TS);
                wmma::load_matrix_sync(bf[1], &smf[ATT_VS(buf) + k8*TS + wn*32 + 16], TS);
                cvt_frag(af); cvt_frag(bf[0]); cvt_frag(bf[1]);
                wmma::mma_sync(pacc[0], af, bf[0], pacc[0]);
                wmma::mma_sync(pacc[1], af, bf[1], pacc[1]);
            }
            wmma::store_matrix_sync(&smf[ATT_OS + (wm*16)*TS + wn*32 +  0], pacc[0], TS, wmma::mem_row_major);
            wmma::store_matrix_sync(&smf[ATT_OS + (wm*16)*TS + wn*32 + 16], pacc[1], TS, wmma::mem_row_major);
        }
        __syncthreads();                                  // [3] Os visible

        {
            const float* pv = &smf[ATT_OS + trow*TS + tseg*16];
#pragma unroll
            for (int j=0;j<16;j++) o[j] += pv[j];
        }
        if (kt + 1 < SEQ/64) CPA_WAIT(0);
        __syncthreads();                                  // [4] new K/V visible; Os free
    }

    // writeout: g_O (b,s,e) with e = h*64 + d
    const float inv = 1.0f / l_i;
    const int qrow = qb*64 + trow;
    float* dst = &g_O[((size_t)bb*SEQ + qrow)*EMBED + h*HDIM + tseg*16];
#pragma unroll
    for (int j4=0;j4<4;j4++){
        float4 v = make_float4(o[j4*4+0]*inv, o[j4*4+1]*inv, o[j4*4+2]*inv, o[j4*4+3]*inv);
        *(float4*)&dst[j4*4] = v;
    }
}

// ---------------------------------------------------------------------------
extern "C" void kernel_launch(void* const* d_in, const int* in_sizes, int n_in,
                              void* d_out, int out_size)
{
    const float* x     = (const float*)d_in[0];
    const int*   mask  = (const int*)  d_in[1];
    const float* w_qkv = (const float*)d_in[2];
    const float* b_qkv = (const float*)d_in[3];
    const float* w_out = (const float*)d_in[4];
    const float* b_out = (const float*)d_in[5];
    float* out = (float*)d_out;

    cudaFuncSetAttribute(proj_gemm,  cudaFuncAttributeMaxDynamicSharedMemorySize, PROJ_SMEM);
    cudaFuncSetAttribute(attn_kernel,cudaFuncAttributeMaxDynamicSharedMemorySize, ATT_SMEM);

    proj_gemm <<<dim3(3*EMBED/128, MROWS/128), 256, PROJ_SMEM>>>(x, w_qkv, b_qkv, nullptr, 3*EMBED, 0);
    attn_kernel<<<dim3(SEQ/64, NHEADS, BATCH), 256, ATT_SMEM>>>(mask);
    proj_gemm <<<dim3(EMBED/128, MROWS/128), 256, PROJ_SMEM>>>(nullptr, w_out, b_out, out, EMBED, 1);
}

// round 11
// speedup vs baseline: 1.2977x; 1.0532x over previous
#include <cuda_runtime.h>
#include <mma.h>
#include <cstdint>
using namespace nvcuda;

#define EMBED  1024
#define NHEADS 16
#define HDIM   64
#define BATCH  4
#define SEQ    2048
#define MROWS  (BATCH*SEQ)   /* 8192 */

// Scratch (static __device__, no allocation)
__device__ float g_Q [BATCH*NHEADS*SEQ*HDIM];   // (b,h,s,d)   tf32-rounded
__device__ float g_Kt[BATCH*NHEADS*HDIM*SEQ];   // (b,h,d,s)   tf32-rounded
__device__ float g_V [BATCH*NHEADS*SEQ*HDIM];   // (b,h,s,d)   tf32-rounded
__device__ float g_O [BATCH*SEQ*EMBED];         // (b,s,e)     tf32-rounded
__device__ float g_X32[MROWS*EMBED];            // x, tf32-rounded
__device__ float g_W1 [EMBED*3*EMBED];          // w_qkv, tf32-rounded
__device__ float g_W2 [EMBED*EMBED];            // w_out, tf32-rounded

__device__ __forceinline__ float ex2a(float x){
    float y; asm("ex2.approx.f32 %0, %1;" : "=f"(y) : "f"(x)); return y;
}
__device__ __forceinline__ float t32(float x){ return wmma::__float_to_tf32(x); }
__device__ __forceinline__ uint32_t smem_u32(const void* p){
    uint32_t a;
    asm("{ .reg .u64 t; cvta.to.shared.u64 t, %1; cvt.u32.u64 %0, t; }" : "=r"(a) : "l"(p));
    return a;
}
__device__ __forceinline__ void cpa16(uint32_t dst, const void* src){
    asm volatile("cp.async.cg.shared.global [%0], [%1], 16;" :: "r"(dst), "l"(src));
}
#define CPA_COMMIT()  asm volatile("cp.async.commit_group;" ::: "memory")
#define CPA_WAIT(N)   asm volatile("cp.async.wait_group %0;" :: "n"(N) : "memory")

// ===========================================================================
// Pre-round: RN fp32->tf32 elementwise into scratch. Idempotent under the
// HMMA truncation, so mainloops need zero per-fragment conversions.
// ===========================================================================
__global__ void round_tf32(const float* __restrict__ src, float* __restrict__ dst, int n4){
    int i = blockIdx.x*blockDim.x + threadIdx.x;
    if (i < n4){
        float4 v = ((const float4*)src)[i];
        v.x = t32(v.x); v.y = t32(v.y); v.z = t32(v.z); v.w = t32(v.w);
        ((float4*)dst)[i] = v;
    }
}

// ===========================================================================
// Projection GEMM: C[128,128] tile of A[M,1024] @ W[1024,Nw] (+bias via MMA).
// BK=32 double-buffered cp.async; inputs pre-rounded tf32; direct gmem
// epilogue (mode 0 = QKV scatter w/ re-round, 1 = final out).
// smem (floats): As0 0, As1 4608, Bs0 9216, Bs1 13440, Ones 17664, Bias 17792
// ===========================================================================
#define PA(buf)   ((buf)*4608)
#define PB(buf)   (9216 + (buf)*4224)
#define P_ONE     17664
#define P_BIAS    17792
#define PROJ_SMEM (18848*4)

__global__ __launch_bounds__(256,2) void proj_gemm(
    const float* __restrict__ Ag, const float* __restrict__ Wg,
    const float* __restrict__ bias,  float* __restrict__ outp,
    int Nw, int mode)
{
    extern __shared__ float smf[];
    const uint32_t sb = smem_u32(smf);
    const int tid = threadIdx.x, wid = tid >> 5;
    const int wm = wid & 1, wn = wid >> 1;
    const int n0 = blockIdx.x * 128, m0 = blockIdx.y * 128;

    // stage chunk 0 (A 128x32, B 32x128)
#pragma unroll
    for (int j=0;j<4;j++){
        int idx = tid + j*256;
        int r = idx >> 3, c4 = (idx & 7)*4;
        cpa16(sb + (PA(0) + r*36 + c4)*4, &Ag[(size_t)(m0+r)*EMBED + c4]);
        int br = idx >> 5, bc = (idx & 31)*4;
        cpa16(sb + (PB(0) + br*132 + bc)*4, &Wg[(size_t)br*Nw + n0 + bc]);
    }
    CPA_COMMIT();

    // ones/bias (rounded at staging; scalar stores)
    if (tid < 128) smf[P_ONE + tid] = ((tid & 7) == 0) ? 1.0f : 0.0f;
    for (int idx = tid; idx < 1056; idx += 256){
        int r = idx / 132, c = idx % 132;
        smf[P_BIAS + idx] = (r == 0 && c < 128) ? t32(bias[n0 + c]) : 0.0f;
    }
    __syncthreads();

    wmma::fragment<wmma::accumulator,16,16,8,float> acc[4][2];
    {
        wmma::fragment<wmma::matrix_a,16,16,8,wmma::precision::tf32,wmma::row_major> a1;
        wmma::fragment<wmma::matrix_b,16,16,8,wmma::precision::tf32,wmma::row_major> bb[2];
        wmma::load_matrix_sync(a1, &smf[P_ONE], 8);
        wmma::load_matrix_sync(bb[0], &smf[P_BIAS + wn*32 +  0], 132);
        wmma::load_matrix_sync(bb[1], &smf[P_BIAS + wn*32 + 16], 132);
#pragma unroll
        for (int i=0;i<4;i++)
#pragma unroll
            for (int f=0;f<2;f++){
                wmma::fill_fragment(acc[i][f], 0.0f);
                wmma::mma_sync(acc[i][f], a1, bb[f], acc[i][f]);
            }
    }

    for (int c = 0; c < 32; c++){
        const int buf = c & 1;
        if (c < 31){
            const int kt = (c+1)*32, nb = buf ^ 1;
#pragma unroll
            for (int j=0;j<4;j++){
                int idx = tid + j*256;
                int r = idx >> 3, c4 = (idx & 7)*4;
                cpa16(sb + (PA(nb) + r*36 + c4)*4, &Ag[(size_t)(m0+r)*EMBED + kt + c4]);
                int br = idx >> 5, bc = (idx & 31)*4;
                cpa16(sb + (PB(nb) + br*132 + bc)*4, &Wg[(size_t)(kt+br)*Nw + n0 + bc]);
            }
            CPA_COMMIT();
            CPA_WAIT(1);
        } else {
            CPA_WAIT(0);
        }
        __syncthreads();

        const float* As = &smf[PA(buf)];
        const float* Bs = &smf[PB(buf)];
#pragma unroll
        for (int k8=0;k8<32;k8+=8){
            wmma::fragment<wmma::matrix_a,16,16,8,wmma::precision::tf32,wmma::row_major> af[4];
            wmma::fragment<wmma::matrix_b,16,16,8,wmma::precision::tf32,wmma::row_major> bf[2];
#pragma unroll
            for (int i=0;i<4;i++)
                wmma::load_matrix_sync(af[i], &As[(wm*64+i*16)*36 + k8], 36);
#pragma unroll
            for (int f=0;f<2;f++)
                wmma::load_matrix_sync(bf[f], &Bs[k8*132 + wn*32 + f*16], 132);
#pragma unroll
            for (int i=0;i<4;i++)
#pragma unroll
                for (int f=0;f<2;f++)
                    wmma::mma_sync(acc[i][f], af[i], bf[f], acc[i][f]);
        }
        __syncthreads();
    }

    // direct-to-gmem epilogue
#pragma unroll
    for (int f=0; f<2; f++){
        const int nc = n0 + wn*32 + f*16;
#pragma unroll
        for (int i=0; i<4; i++){
            const int mr = m0 + wm*64 + i*16;
            if (mode == 1){
                wmma::store_matrix_sync(&outp[(size_t)mr*EMBED + nc], acc[i][f],
                                        EMBED, wmma::mem_row_major);
            } else {
                // round so attention consumes exact-tf32 operands
#pragma unroll
                for (int t=0; t<acc[i][f].num_elements; t++)
                    acc[i][f].x[t] = t32(acc[i][f].x[t]);
                const int three = n0 >> 10;
                const int h  = (nc & 1023) >> 6, d0 = nc & 63;
                const int bb = mr >> 11, s0 = mr & 2047;
                if (three == 1){
                    wmma::store_matrix_sync(
                        &g_Kt[((size_t)(bb*NHEADS + h)*HDIM + d0)*SEQ + s0],
                        acc[i][f], SEQ, wmma::mem_col_major);
                } else {
                    float* dst = three ? g_V : g_Q;
                    wmma::store_matrix_sync(
                        &dst[((size_t)(bb*NHEADS + h)*SEQ + s0)*HDIM + d0],
                        acc[i][f], HDIM, wmma::mem_row_major);
                }
            }
        }
    }
}

// ===========================================================================
// Flash attention, wmma tf32 + cp.async prefetch. All MMA operands are
// exact-tf32 (Q/K/V pre-rounded; P rounded in the scalar softmax) -> no cvt.
// smem (floats): Qs 0, Ks 4352, Vs0 8704, Vs1 13056, Ss 17408, Os 21760
// ===========================================================================
#define ATT_QS 0
#define ATT_KS 4352
#define ATT_VS(b) (8704 + (b)*4352)
#define ATT_SS 17408
#define ATT_OS 21760
#define ATT_SMEM (26112*4)
#define TS 68

__global__ __launch_bounds__(256,2) void attn_kernel(const int* __restrict__ mask)
{
    extern __shared__ float smf[];
    const uint32_t sb = smem_u32(smf);

    const int qb = blockIdx.x, h = blockIdx.y, bb = blockIdx.z;
    const int tid = threadIdx.x, wid = tid >> 5;
    const int wm = wid & 3, wn = wid >> 2;
    const int trow = tid >> 2, tseg = tid & 3;

    const float* Qg = g_Q  + ((size_t)(bb*NHEADS + h)*SEQ + qb*64)*HDIM;
    const float* Kg = g_Kt +  (size_t)(bb*NHEADS + h)*HDIM*SEQ;
    const float* Vg = g_V  +  (size_t)(bb*NHEADS + h)*SEQ*HDIM;
    const int*   Mg = mask +  ((size_t)bb*SEQ + qb*64)*SEQ;

    // prologue: stage Q, K0, V0
#pragma unroll
    for (int j=0;j<4;j++){
        int idx = tid + j*256;
        int r = idx >> 4, c4 = (idx & 15)*4;
        cpa16(sb + (ATT_QS    + r*TS + c4)*4, &Qg[r*HDIM + c4]);
        cpa16(sb + (ATT_KS    + r*TS + c4)*4, &Kg[(size_t)r*SEQ + c4]);
        cpa16(sb + (ATT_VS(0) + r*TS + c4)*4, &Vg[(size_t)r*HDIM + c4]);
    }
    CPA_COMMIT();
    CPA_WAIT(0);
    __syncthreads();

    float o[16];
#pragma unroll
    for (int j=0;j<16;j++) o[j]=0.f;
    float m_i = -1e30f, l_i = 0.f;
    const float CE = 0.18033688011112042f;   // log2(e)/sqrt(64)

    for (int kt = 0; kt < SEQ/64; kt++){
        const int buf = kt & 1;
        const int k0 = kt*64;

        // S = Q @ K^T (Ks is d-major: row=d, col=key)
        {
            wmma::fragment<wmma::accumulator,16,16,8,float> sacc[2];
            wmma::fill_fragment(sacc[0], 0.f);
            wmma::fill_fragment(sacc[1], 0.f);
#pragma unroll
            for (int k8=0;k8<64;k8+=8){
                wmma::fragment<wmma::matrix_a,16,16,8,wmma::precision::tf32,wmma::row_major> af;
                wmma::fragment<wmma::matrix_b,16,16,8,wmma::precision::tf32,wmma::row_major> bf[2];
                wmma::load_matrix_sync(af, &smf[ATT_QS + (wm*16)*TS + k8], TS);
                wmma::load_matrix_sync(bf[0], &smf[ATT_KS + k8*TS + wn*32 +  0], TS);
                wmma::load_matrix_sync(bf[1], &smf[ATT_KS + k8*TS + wn*32 + 16], TS);
                wmma::mma_sync(sacc[0], af, bf[0], sacc[0]);
                wmma::mma_sync(sacc[1], af, bf[1], sacc[1]);
            }
            wmma::store_matrix_sync(&smf[ATT_SS + (wm*16)*TS + wn*32 +  0], sacc[0], TS, wmma::mem_row_major);
            wmma::store_matrix_sync(&smf[ATT_SS + (wm*16)*TS + wn*32 + 16], sacc[1], TS, wmma::mem_row_major);
        }
        __syncthreads();                                  // [1] S visible; Ks free

        // prefetch next K and next V (into alternate V buffer)
        if (kt + 1 < SEQ/64){
            const int kn = k0 + 64;
#pragma unroll
            for (int j=0;j<4;j++){
                int idx = tid + j*256;
                int r = idx >> 4, c4 = (idx & 15)*4;
                cpa16(sb + (ATT_KS + r*TS + c4)*4,        &Kg[(size_t)r*SEQ + kn + c4]);
                cpa16(sb + (ATT_VS(buf^1) + r*TS + c4)*4, &Vg[(size_t)(kn+r)*HDIM + c4]);
            }
            CPA_COMMIT();
        }

        // online softmax on row trow, cols tseg*16..+15; P stored tf32-exact
        {
            float s[16];
            const int* mrow = Mg + (size_t)trow*SEQ + k0 + tseg*16;
            float* srow = &smf[ATT_SS + trow*TS + tseg*16];
#pragma unroll
            for (int j4=0;j4<4;j4++){
                float4 sv = *(const float4*)&srow[j4*4];
                int4   mv = *(const int4*)&mrow[j4*4];
                s[j4*4+0] = mv.x ? sv.x : -1e30f;
                s[j4*4+1] = mv.y ? sv.y : -1e30f;
                s[j4*4+2] = mv.z ? sv.z : -1e30f;
                s[j4*4+3] = mv.w ? sv.w : -1e30f;
            }
            float rm = s[0];
#pragma unroll
            for (int j=1;j<16;j++) rm = fmaxf(rm, s[j]);
            rm = fmaxf(rm, __shfl_xor_sync(0xffffffffu, rm, 1));
            rm = fmaxf(rm, __shfl_xor_sync(0xffffffffu, rm, 2));
            const float mn = fmaxf(m_i, rm);
            const float alpha = ex2a((m_i - mn)*CE);
            m_i = mn;
            float rs = 0.f;
#pragma unroll
            for (int j=0;j<16;j++){
                float p = ex2a((s[j] - mn)*CE);
                rs += p;
                srow[j] = t32(p);
            }
            rs += __shfl_xor_sync(0xffffffffu, rs, 1);
            rs += __shfl_xor_sync(0xffffffffu, rs, 2);
            l_i = l_i*alpha + rs;
#pragma unroll
            for (int j=0;j<16;j++) o[j] *= alpha;
        }
        __syncthreads();                                  // [2] P visible

        // PV = P @ V -> Os
        {
            wmma::fragment<wmma::accumulator,16,16,8,float> pacc[2];
            wmma::fill_fragment(pacc[0], 0.f);
            wmma::fill_fragment(pacc[1], 0.f);
#pragma unroll
            for (int k8=0;k8<64;k8+=8){
                wmma::fragment<wmma::matrix_a,16,16,8,wmma::precision::tf32,wmma::row_major> af;
                wmma::fragment<wmma::matrix_b,16,16,8,wmma::precision::tf32,wmma::row_major> bf[2];
                wmma::load_matrix_sync(af, &smf[ATT_SS + (wm*16)*TS + k8], TS);
                wmma::load_matrix_sync(bf[0], &smf[ATT_VS(buf) + k8*TS + wn*32 +  0], TS);
                wmma::load_matrix_sync(bf[1], &smf[ATT_VS(buf) + k8*TS + wn*32 + 16], TS);
                wmma::mma_sync(pacc[0], af, bf[0], pacc[0]);
                wmma::mma_sync(pacc[1], af, bf[1], pacc[1]);
            }
            wmma::store_matrix_sync(&smf[ATT_OS + (wm*16)*TS + wn*32 +  0], pacc[0], TS, wmma::mem_row_major);
            wmma::store_matrix_sync(&smf[ATT_OS + (wm*16)*TS + wn*32 + 16], pacc[1], TS, wmma::mem_row_major);
        }
        __syncthreads();                                  // [3] Os visible

        {
            const float* pv = &smf[ATT_OS + trow*TS + tseg*16];
#pragma unroll
            for (int j=0;j<16;j++) o[j] += pv[j];
        }
        if (kt + 1 < SEQ/64) CPA_WAIT(0);
        __syncthreads();                                  // [4] new K/V visible; Os free
    }

    // writeout: g_O (b,s,e), tf32-rounded so out_gemm consumes exact tf32
    const float inv = 1.0f / l_i;
    const int qrow = qb*64 + trow;
    float* dst = &g_O[((size_t)bb*SEQ + qrow)*EMBED + h*HDIM + tseg*16];
#pragma unroll
    for (int j4=0;j4<4;j4++){
        float4 v = make_float4(t32(o[j4*4+0]*inv), t32(o[j4*4+1]*inv),
                               t32(o[j4*4+2]*inv), t32(o[j4*4+3]*inv));
        *(float4*)&dst[j4*4] = v;
    }
}

// ---------------------------------------------------------------------------
extern "C" void kernel_launch(void* const* d_in, const int* in_sizes, int n_in,
                              void* d_out, int out_size)
{
    const float* x     = (const float*)d_in[0];
    const int*   mask  = (const int*)  d_in[1];
    const float* w_qkv = (const float*)d_in[2];
    const float* b_qkv = (const float*)d_in[3];
    const float* w_out = (const float*)d_in[4];
    const float* b_out = (const float*)d_in[5];
    float* out = (float*)d_out;

    cudaFuncSetAttribute(proj_gemm,  cudaFuncAttributeMaxDynamicSharedMemorySize, PROJ_SMEM);
    cudaFuncSetAttribute(attn_kernel,cudaFuncAttributeMaxDynamicSharedMemorySize, ATT_SMEM);

    float* x32; float* w1; float* w2;
    cudaGetSymbolAddress((void**)&x32, g_X32);
    cudaGetSymbolAddress((void**)&w1,  g_W1);
    cudaGetSymbolAddress((void**)&w2,  g_W2);

    round_tf32<<<(MROWS*EMBED/4 + 255)/256, 256>>>(x,     x32, MROWS*EMBED/4);
    round_tf32<<<(EMBED*3*EMBED/4 + 255)/256, 256>>>(w_qkv, w1, EMBED*3*EMBED/4);
    round_tf32<<<(EMBED*EMBED/4 + 255)/256, 256>>>(w_out,  w2, EMBED*EMBED/4);

    proj_gemm <<<dim3(3*EMBED/128, MROWS/128), 256, PROJ_SMEM>>>(x32, w1, b_qkv, nullptr, 3*EMBED, 0);
    attn_kernel<<<dim3(SEQ/64, NHEADS, BATCH), 256, ATT_SMEM>>>(mask);

    float* o32; cudaGetSymbolAddress((void**)&o32, g_O);
    proj_gemm <<<dim3(EMBED/128, MROWS/128), 256, PROJ_SMEM>>>(o32, w2, b_out, out, EMBED, 1);
}

// round 13
// speedup vs baseline: 3.5330x; 2.7225x over previous
#include <cuda_runtime.h>
#include <cuda_fp16.h>
#include <mma.h>
#include <cstdint>
using namespace nvcuda;

#define EMBED  1024
#define NHEADS 16
#define HDIM   64
#define BATCH  4
#define SEQ    2048
#define MROWS  (BATCH*SEQ)   /* 8192 */

// Scratch (static __device__, no allocation) — all operands fp16, accum fp32
__device__ __half g_Qh [BATCH*NHEADS*SEQ*HDIM];   // (b,h,s,d)
__device__ __half g_Kh [BATCH*NHEADS*SEQ*HDIM];   // (b,h,s,d)  (no transpose)
__device__ __half g_Vh [BATCH*NHEADS*SEQ*HDIM];   // (b,h,s,d)
__device__ __half g_Oh [BATCH*SEQ*EMBED];         // (b,s,e)
__device__ __half g_X16[MROWS*EMBED];
__device__ __half g_W1h[EMBED*3*EMBED];
__device__ __half g_W2h[EMBED*EMBED];

__device__ __forceinline__ float ex2a(float x){
    float y; asm("ex2.approx.f32 %0, %1;" : "=f"(y) : "f"(x)); return y;
}
__device__ __forceinline__ uint32_t smem_u32(const void* p){
    uint32_t a;
    asm("{ .reg .u64 t; cvta.to.shared.u64 t, %1; cvt.u32.u64 %0, t; }" : "=r"(a) : "l"(p));
    return a;
}
__device__ __forceinline__ void cpa16(uint32_t dst, const void* src){
    asm volatile("cp.async.cg.shared.global [%0], [%1], 16;" :: "r"(dst), "l"(src));
}
#define CPA_COMMIT()  asm volatile("cp.async.commit_group;" ::: "memory")
#define CPA_WAIT(N)   asm volatile("cp.async.wait_group %0;" :: "n"(N) : "memory")

// fp32 -> fp16 RN pre-convert (8 elements/thread)
__global__ void f2h(const float* __restrict__ s, __half* __restrict__ d, int n8){
    int i = blockIdx.x*blockDim.x + threadIdx.x;
    if (i < n8){
        float4 a = ((const float4*)s)[i*2], b = ((const float4*)s)[i*2+1];
        __half2* o = (__half2*)d + i*4;
        o[0] = __floats2half2_rn(a.x, a.y);
        o[1] = __floats2half2_rn(a.z, a.w);
        o[2] = __floats2half2_rn(b.x, b.y);
        o[3] = __floats2half2_rn(b.z, b.w);
    }
}

// ===========================================================================
// Projection GEMM (fp16 in, fp32 accum): C[128,128] of A[M,1024]@W[1024,Nw].
// BK=32 double-buffered cp.async; smem-staged fp32 epilogue (+bias).
// mode 0 = scatter Q/K/V (half), 1 = final out (float).
// smem bytes: A bufs 128x40h @ 0/10240, B bufs 32x136h @ 20480/29184;
//             epilogue overlays Cs fp32 128x132 @ 0 (67584 B total)
// ===========================================================================
#define PA(b) ((b)*10240)
#define PB(b) (20480 + (b)*8704)
#define PROJ_SMEM 67584

__global__ __launch_bounds__(256,2) void proj_gemm(
    const __half* __restrict__ Ag, const __half* __restrict__ Wg,
    const float* __restrict__ bias, float* __restrict__ outp,
    int Nw, int mode)
{
    extern __shared__ char smc[];
    const uint32_t sb = smem_u32(smc);
    __half* smh = (__half*)smc;
    float*  Cs  = (float*)smc;
    const int tid = threadIdx.x, wid = tid >> 5;
    const int wm = wid & 1, wn = wid >> 1;
    const int n0 = blockIdx.x * 128, m0 = blockIdx.y * 128;

    // stage chunk 0: A 128x32h (row=4 chunks), B 32x128h (row=16 chunks)
#pragma unroll
    for (int j=0;j<2;j++){
        int idx = tid + j*256;
        int r = idx >> 2, c8 = (idx & 3)*8;
        cpa16(sb + PA(0) + (r*40 + c8)*2, &Ag[(size_t)(m0+r)*EMBED + c8]);
        int br = idx >> 4, bc8 = (idx & 15)*8;
        cpa16(sb + PB(0) + (br*136 + bc8)*2, &Wg[(size_t)br*Nw + n0 + bc8]);
    }
    CPA_COMMIT();

    wmma::fragment<wmma::accumulator,16,16,16,float> acc[4][2];
#pragma unroll
    for (int i=0;i<4;i++)
#pragma unroll
        for (int f=0;f<2;f++) wmma::fill_fragment(acc[i][f], 0.0f);

    for (int c = 0; c < 32; c++){
        const int buf = c & 1;
        if (c < 31){
            const int kt = (c+1)*32, nb = buf ^ 1;
#pragma unroll
            for (int j=0;j<2;j++){
                int idx = tid + j*256;
                int r = idx >> 2, c8 = (idx & 3)*8;
                cpa16(sb + PA(nb) + (r*40 + c8)*2, &Ag[(size_t)(m0+r)*EMBED + kt + c8]);
                int br = idx >> 4, bc8 = (idx & 15)*8;
                cpa16(sb + PB(nb) + (br*136 + bc8)*2, &Wg[(size_t)(kt+br)*Nw + n0 + bc8]);
            }
            CPA_COMMIT();
            CPA_WAIT(1);
        } else {
            CPA_WAIT(0);
        }
        __syncthreads();

        const __half* As = smh + PA(buf)/2;
        const __half* Bs = smh + PB(buf)/2;
#pragma unroll
        for (int k16=0;k16<32;k16+=16){
            wmma::fragment<wmma::matrix_a,16,16,16,__half,wmma::row_major> af[4];
            wmma::fragment<wmma::matrix_b,16,16,16,__half,wmma::row_major> bf[2];
#pragma unroll
            for (int i=0;i<4;i++)
                wmma::load_matrix_sync(af[i], &As[(wm*64+i*16)*40 + k16], 40);
#pragma unroll
            for (int f=0;f<2;f++)
                wmma::load_matrix_sync(bf[f], &Bs[k16*136 + wn*32 + f*16], 136);
#pragma unroll
            for (int i=0;i<4;i++)
#pragma unroll
                for (int f=0;f<2;f++)
                    wmma::mma_sync(acc[i][f], af[i], bf[f], acc[i][f]);
        }
        __syncthreads();
    }

    // epilogue: stage fp32 C in smem, then add bias + scatter
#pragma unroll
    for (int i=0;i<4;i++)
#pragma unroll
        for (int f=0;f<2;f++)
            wmma::store_matrix_sync(&Cs[(wm*64+i*16)*132 + wn*32 + f*16],
                                    acc[i][f], 132, wmma::mem_row_major);
    __syncthreads();

    if (mode == 1){
#pragma unroll
        for (int j=0;j<16;j++){
            int idx = tid + j*256;
            int r = idx >> 5, c4 = (idx & 31)*4;
            float4 b4 = *(const float4*)&bias[n0 + c4];
            float4 v;
            v.x = Cs[r*132+c4+0] + b4.x;
            v.y = Cs[r*132+c4+1] + b4.y;
            v.z = Cs[r*132+c4+2] + b4.z;
            v.w = Cs[r*132+c4+3] + b4.w;
            *(float4*)&outp[(size_t)(m0+r)*EMBED + n0 + c4] = v;
        }
    } else {
        const int three = n0 >> 10;
        __half* dst0 = (three == 0) ? g_Qh : (three == 1) ? g_Kh : g_Vh;
#pragma unroll
        for (int j=0;j<16;j++){
            int idx = tid + j*256;
            int r = idx >> 5, c4 = (idx & 31)*4;
            int n = n0 + c4;
            int h = (n & 1023) >> 6, d0 = n & 63;
            int row = m0 + r;
            int bb = row >> 11, s0 = row & 2047;
            float4 b4 = *(const float4*)&bias[n];
            __half2 h0 = __floats2half2_rn(Cs[r*132+c4+0] + b4.x, Cs[r*132+c4+1] + b4.y);
            __half2 h1 = __floats2half2_rn(Cs[r*132+c4+2] + b4.z, Cs[r*132+c4+3] + b4.w);
            __half2* dp = (__half2*)&dst0[((size_t)(bb*NHEADS + h)*SEQ + s0)*HDIM + d0];
            dp[0] = h0; dp[1] = h1;
        }
    }
}

// ===========================================================================
// Flash attention, fp16 wmma + cp.async prefetch.
// smem bytes: Qh@0, Kh@9216, Vh(b)@18432+9216b, Ph@36864 (all 64x72 half);
//             Ss fp32 64x68 @46080, Os fp32 64x68 @63488. Total 80896.
// ===========================================================================
#define AQ 0
#define AK 9216
#define AV(b) (18432 + (b)*9216)
#define AP 36864
#define ASSB 46080
#define AOSB 63488
#define ATT_SMEM 80896

__global__ __launch_bounds__(256,2) void attn_kernel(const int* __restrict__ mask)
{
    extern __shared__ char smc[];
    const uint32_t sb = smem_u32(smc);
    __half* Qh = (__half*)(smc + AQ);
    __half* Kh = (__half*)(smc + AK);
    __half* Ph = (__half*)(smc + AP);
    float*  Ssf = (float*)(smc + ASSB);
    float*  Osf = (float*)(smc + AOSB);

    const int qb = blockIdx.x, h = blockIdx.y, bb = blockIdx.z;
    const int tid = threadIdx.x, wid = tid >> 5;
    const int wm = wid & 3, wn = wid >> 2;
    const int trow = tid >> 2, tseg = tid & 3;

    const __half* Qg = g_Qh + ((size_t)(bb*NHEADS + h)*SEQ + qb*64)*HDIM;
    const __half* Kg = g_Kh +  (size_t)(bb*NHEADS + h)*SEQ*HDIM;
    const __half* Vg = g_Vh +  (size_t)(bb*NHEADS + h)*SEQ*HDIM;
    const int*    Mg = mask +  ((size_t)bb*SEQ + qb*64)*SEQ;

    // prologue: stage Q, K0, V0 (rows of 64 half = 8 chunks)
#pragma unroll
    for (int j=0;j<2;j++){
        int idx = tid + j*256;
        int r = idx >> 3, c8 = (idx & 7)*8;
        cpa16(sb + AQ    + (r*72 + c8)*2, &Qg[(size_t)r*HDIM + c8]);
        cpa16(sb + AK    + (r*72 + c8)*2, &Kg[(size_t)r*HDIM + c8]);
        cpa16(sb + AV(0) + (r*72 + c8)*2, &Vg[(size_t)r*HDIM + c8]);
    }
    CPA_COMMIT();
    CPA_WAIT(0);
    __syncthreads();

    float o[16];
#pragma unroll
    for (int j=0;j<16;j++) o[j]=0.f;
    float m_i = -1e30f, l_i = 0.f;
    const float CE = 0.18033688011112042f;   // log2(e)/sqrt(64)

    for (int kt = 0; kt < SEQ/64; kt++){
        const int buf = kt & 1;
        const int k0 = kt*64;
        __half* Vh = (__half*)(smc + AV(buf));

        // S = Q @ K^T : A = Q row-major, B = K col_major (K stored [key][d])
        {
            wmma::fragment<wmma::accumulator,16,16,16,float> sacc[2];
            wmma::fill_fragment(sacc[0], 0.f);
            wmma::fill_fragment(sacc[1], 0.f);
#pragma unroll
            for (int k16=0;k16<64;k16+=16){
                wmma::fragment<wmma::matrix_a,16,16,16,__half,wmma::row_major> af;
                wmma::fragment<wmma::matrix_b,16,16,16,__half,wmma::col_major> bf[2];
                wmma::load_matrix_sync(af, &Qh[(wm*16)*72 + k16], 72);
                wmma::load_matrix_sync(bf[0], &Kh[(wn*32 +  0)*72 + k16], 72);
                wmma::load_matrix_sync(bf[1], &Kh[(wn*32 + 16)*72 + k16], 72);
                wmma::mma_sync(sacc[0], af, bf[0], sacc[0]);
                wmma::mma_sync(sacc[1], af, bf[1], sacc[1]);
            }
            wmma::store_matrix_sync(&Ssf[(wm*16)*68 + wn*32 +  0], sacc[0], 68, wmma::mem_row_major);
            wmma::store_matrix_sync(&Ssf[(wm*16)*68 + wn*32 + 16], sacc[1], 68, wmma::mem_row_major);
        }
        __syncthreads();                                  // [1] S visible; Kh free

        // prefetch next K (into Kh) and next V (alternate buffer)
        if (kt + 1 < SEQ/64){
            const int kn = k0 + 64;
#pragma unroll
            for (int j=0;j<2;j++){
                int idx = tid + j*256;
                int r = idx >> 3, c8 = (idx & 7)*8;
                cpa16(sb + AK        + (r*72 + c8)*2, &Kg[(size_t)(kn+r)*HDIM + c8]);
                cpa16(sb + AV(buf^1) + (r*72 + c8)*2, &Vg[(size_t)(kn+r)*HDIM + c8]);
            }
            CPA_COMMIT();
        }

        // online softmax on row trow, cols tseg*16..+15; P stored as half
        {
            float s[16];
            const int* mrow = Mg + (size_t)trow*SEQ + k0 + tseg*16;
            const float* srow = &Ssf[trow*68 + tseg*16];
            __half* prow = &Ph[trow*72 + tseg*16];
#pragma unroll
            for (int j4=0;j4<4;j4++){
                float4 sv = *(const float4*)&srow[j4*4];
                int4   mv = *(const int4*)&mrow[j4*4];
                s[j4*4+0] = mv.x ? sv.x : -1e30f;
                s[j4*4+1] = mv.y ? sv.y : -1e30f;
                s[j4*4+2] = mv.z ? sv.z : -1e30f;
                s[j4*4+3] = mv.w ? sv.w : -1e30f;
            }
            float rm = s[0];
#pragma unroll
            for (int j=1;j<16;j++) rm = fmaxf(rm, s[j]);
            rm = fmaxf(rm, __shfl_xor_sync(0xffffffffu, rm, 1));
            rm = fmaxf(rm, __shfl_xor_sync(0xffffffffu, rm, 2));
            const float mn = fmaxf(m_i, rm);
            const float alpha = ex2a((m_i - mn)*CE);
            m_i = mn;
            float rs = 0.f;
#pragma unroll
            for (int j=0;j<16;j++){
                float p = ex2a((s[j] - mn)*CE);
                __half ph = __float2half_rn(p);
                prow[j] = ph;
                rs += __half2float(ph);   // l matches the P actually used by MMA
            }
            rs += __shfl_xor_sync(0xffffffffu, rs, 1);
            rs += __shfl_xor_sync(0xffffffffu, rs, 2);
            l_i = l_i*alpha + rs;
#pragma unroll
            for (int j=0;j<16;j++) o[j] *= alpha;
        }
        __syncthreads();                                  // [2] P visible

        // PV = P @ V -> Os (fp32)
        {
            wmma::fragment<wmma::accumulator,16,16,16,float> pacc[2];
            wmma::fill_fragment(pacc[0], 0.f);
            wmma::fill_fragment(pacc[1], 0.f);
#pragma unroll
            for (int k16=0;k16<64;k16+=16){
                wmma::fragment<wmma::matrix_a,16,16,16,__half,wmma::row_major> af;
                wmma::fragment<wmma::matrix_b,16,16,16,__half,wmma::row_major> bf[2];
                wmma::load_matrix_sync(af, &Ph[(wm*16)*72 + k16], 72);
                wmma::load_matrix_sync(bf[0], &Vh[k16*72 + wn*32 +  0], 72);
                wmma::load_matrix_sync(bf[1], &Vh[k16*72 + wn*32 + 16], 72);
                wmma::mma_sync(pacc[0], af, bf[0], pacc[0]);
                wmma::mma_sync(pacc[1], af, bf[1], pacc[1]);
            }
            wmma::store_matrix_sync(&Osf[(wm*16)*68 + wn*32 +  0], pacc[0], 68, wmma::mem_row_major);
            wmma::store_matrix_sync(&Osf[(wm*16)*68 + wn*32 + 16], pacc[1], 68, wmma::mem_row_major);
        }
        __syncthreads();                                  // [3] Os visible

        {
            const float* pv = &Osf[trow*68 + tseg*16];
#pragma unroll
            for (int j=0;j<16;j++) o[j] += pv[j];
        }
        if (kt + 1 < SEQ/64) CPA_WAIT(0);
        __syncthreads();                                  // [4] new K/V visible; Os free
    }

    // writeout: g_Oh (b,s,e) half, e = h*64 + d
    const float inv = 1.0f / l_i;
    const int qrow = qb*64 + trow;
    __half2* dst = (__half2*)&g_Oh[((size_t)bb*SEQ + qrow)*EMBED + h*HDIM + tseg*16];
#pragma unroll
    for (int j2=0;j2<8;j2++)
        dst[j2] = __floats2half2_rn(o[j2*2]*inv, o[j2*2+1]*inv);
}

// ---------------------------------------------------------------------------
extern "C" void kernel_launch(void* const* d_in, const int* in_sizes, int n_in,
                              void* d_out, int out_size)
{
    const float* x     = (const float*)d_in[0];
    const int*   mask  = (const int*)  d_in[1];
    const float* w_qkv = (const float*)d_in[2];
    const float* b_qkv = (const float*)d_in[3];
    const float* w_out = (const float*)d_in[4];
    const float* b_out = (const float*)d_in[5];
    float* out = (float*)d_out;

    cudaFuncSetAttribute(proj_gemm,  cudaFuncAttributeMaxDynamicSharedMemorySize, PROJ_SMEM);
    cudaFuncSetAttribute(attn_kernel,cudaFuncAttributeMaxDynamicSharedMemorySize, ATT_SMEM);

    __half *x16, *w1h, *w2h, *oh;
    cudaGetSymbolAddress((void**)&x16, g_X16);
    cudaGetSymbolAddress((void**)&w1h, g_W1h);
    cudaGetSymbolAddress((void**)&w2h, g_W2h);
    cudaGetSymbolAddress((void**)&oh,  g_Oh);

    f2h<<<(MROWS*EMBED/8 + 255)/256, 256>>>(x,     x16, MROWS*EMBED/8);
    f2h<<<(EMBED*3*EMBED/8 + 255)/256, 256>>>(w_qkv, w1h, EMBED*3*EMBED/8);
    f2h<<<(EMBED*EMBED/8 + 255)/256, 256>>>(w_out,  w2h, EMBED*EMBED/8);

    proj_gemm <<<dim3(3*EMBED/128, MROWS/128), 256, PROJ_SMEM>>>(x16, w1h, b_qkv, nullptr, 3*EMBED, 0);
    attn_kernel<<<dim3(SEQ/64, NHEADS, BATCH), 256, ATT_SMEM>>>(mask);
    proj_gemm <<<dim3(EMBED/128, MROWS/128), 256, PROJ_SMEM>>>(oh, w2h, b_out, out, EMBED, 1);
}

// round 17
// speedup vs baseline: 3.9931x; 1.1302x over previous
#include <cuda_runtime.h>
#include <cuda_fp16.h>
#include <mma.h>
#include <cstdint>
using namespace nvcuda;

#define EMBED  1024
#define NHEADS 16
#define HDIM   64
#define BATCH  4
#define SEQ    2048
#define MROWS  (BATCH*SEQ)   /* 8192 */

// Scratch (static __device__, no allocation)
__device__ __half g_Qh [BATCH*NHEADS*SEQ*HDIM];
__device__ __half g_Kh [BATCH*NHEADS*SEQ*HDIM];
__device__ __half g_Vh [BATCH*NHEADS*SEQ*HDIM];
__device__ __half g_Oh [BATCH*SEQ*EMBED];
__device__ __half g_X16[MROWS*EMBED];
__device__ __half g_W1h[EMBED*3*EMBED];
__device__ __half g_W2h[EMBED*EMBED];
__device__ int    g_flags[BATCH*32*16];     // 1 = tile all-ones (skip mask)

__device__ __forceinline__ float ex2a(float x){
    float y; asm("ex2.approx.f32 %0, %1;" : "=f"(y) : "f"(x)); return y;
}
__device__ __forceinline__ uint32_t smem_u32(const void* p){
    uint32_t a;
    asm("{ .reg .u64 t; cvta.to.shared.u64 t, %1; cvt.u32.u64 %0, t; }" : "=r"(a) : "l"(p));
    return a;
}
__device__ __forceinline__ void cpa16(uint32_t dst, const void* src){
    asm volatile("cp.async.cg.shared.global [%0], [%1], 16;" :: "r"(dst), "l"(src));
}
#define CPA_COMMIT()  asm volatile("cp.async.commit_group;" ::: "memory")
#define CPA_WAIT(N)   asm volatile("cp.async.wait_group %0;" :: "n"(N) : "memory")

// fp32 -> fp16 RN pre-convert (8 elements/thread)
__global__ void f2h(const float* __restrict__ s, __half* __restrict__ d, int n8){
    int i = blockIdx.x*blockDim.x + threadIdx.x;
    if (i < n8){
        float4 a = ((const float4*)s)[i*2], b = ((const float4*)s)[i*2+1];
        __half2* o = (__half2*)d + i*4;
        o[0] = __floats2half2_rn(a.x, a.y);
        o[1] = __floats2half2_rn(a.z, a.w);
        o[2] = __floats2half2_rn(b.x, b.y);
        o[3] = __floats2half2_rn(b.z, b.w);
    }
}

// Mask pre-scan: flag per (batch, 64-row qtile, 128-col ktile): 1 if all ones.
__global__ __launch_bounds__(256) void mask_scan(const int* __restrict__ mask){
    const int kt = blockIdx.x, qt = blockIdx.y, bz = blockIdx.z;
    const int tid = threadIdx.x;
    const int row = qt*64 + (tid >> 2);
    const int c0  = kt*128 + (tid & 3)*32;
    const int4* p = (const int4*)(mask + ((size_t)bz*SEQ + row)*SEQ + c0);
    int ok = 1;
#pragma unroll
    for (int j=0;j<8;j++){
        int4 v = p[j];
        ok &= (v.x && v.y && v.z && v.w) ? 1 : 0;
    }
    int all = __syncthreads_and(ok);
    if (tid == 0) g_flags[(bz*32 + qt)*16 + kt] = all;
}

// ===========================================================================
// Projection GEMM (fp16 in, fp32 accum): C[128,128] of A[M,1024]@W[1024,Nw].
// BK=64 double-buffered cp.async; smem-staged fp32 epilogue (+bias).
// smem bytes: A bufs 128x72h @ 0/18432, B bufs 64x136h @ 36864/54272 (71680);
//             epilogue overlays Cs fp32 128x132 (67584).
// ===========================================================================
#define PA(b) ((b)*18432)
#define PB(b) (36864 + (b)*17408)
#define PROJ_SMEM 71680

__global__ __launch_bounds__(256,2) void proj_gemm(
    const __half* __restrict__ Ag, const __half* __restrict__ Wg,
    const float* __restrict__ bias, float* __restrict__ outp,
    int Nw, int mode)
{
    extern __shared__ char smc[];
    const uint32_t sb = smem_u32(smc);
    __half* smh = (__half*)smc;
    float*  Cs  = (float*)smc;
    const int tid = threadIdx.x, wid = tid >> 5;
    const int wm = wid & 1, wn = wid >> 1;
    const int n0 = blockIdx.x * 128, m0 = blockIdx.y * 128;

    // stage chunk 0: A 128x64h, B 64x128h
#pragma unroll
    for (int j=0;j<4;j++){
        int idx = tid + j*256;
        int r = idx >> 3, c8 = (idx & 7)*8;
        cpa16(sb + PA(0) + (r*72 + c8)*2, &Ag[(size_t)(m0+r)*EMBED + c8]);
        int br = idx >> 4, bc8 = (idx & 15)*8;
        cpa16(sb + PB(0) + (br*136 + bc8)*2, &Wg[(size_t)br*Nw + n0 + bc8]);
    }
    CPA_COMMIT();

    wmma::fragment<wmma::accumulator,16,16,16,float> acc[4][2];
#pragma unroll
    for (int i=0;i<4;i++)
#pragma unroll
        for (int f=0;f<2;f++) wmma::fill_fragment(acc[i][f], 0.0f);

    for (int c = 0; c < 16; c++){
        const int buf = c & 1;
        if (c < 15){
            const int kt = (c+1)*64, nb = buf ^ 1;
#pragma unroll
            for (int j=0;j<4;j++){
                int idx = tid + j*256;
                int r = idx >> 3, c8 = (idx & 7)*8;
                cpa16(sb + PA(nb) + (r*72 + c8)*2, &Ag[(size_t)(m0+r)*EMBED + kt + c8]);
                int br = idx >> 4, bc8 = (idx & 15)*8;
                cpa16(sb + PB(nb) + (br*136 + bc8)*2, &Wg[(size_t)(kt+br)*Nw + n0 + bc8]);
            }
            CPA_COMMIT();
            CPA_WAIT(1);
        } else {
            CPA_WAIT(0);
        }
        __syncthreads();

        const __half* As = smh + PA(buf)/2;
        const __half* Bs = smh + PB(buf)/2;
#pragma unroll
        for (int k16=0;k16<64;k16+=16){
            wmma::fragment<wmma::matrix_a,16,16,16,__half,wmma::row_major> af[4];
            wmma::fragment<wmma::matrix_b,16,16,16,__half,wmma::row_major> bf[2];
#pragma unroll
            for (int i=0;i<4;i++)
                wmma::load_matrix_sync(af[i], &As[(wm*64+i*16)*72 + k16], 72);
#pragma unroll
            for (int f=0;f<2;f++)
                wmma::load_matrix_sync(bf[f], &Bs[k16*136 + wn*32 + f*16], 136);
#pragma unroll
            for (int i=0;i<4;i++)
#pragma unroll
                for (int f=0;f<2;f++)
                    wmma::mma_sync(acc[i][f], af[i], bf[f], acc[i][f]);
        }
        __syncthreads();
    }

    // epilogue: stage fp32 C in smem, then add bias + scatter
#pragma unroll
    for (int i=0;i<4;i++)
#pragma unroll
        for (int f=0;f<2;f++)
            wmma::store_matrix_sync(&Cs[(wm*64+i*16)*132 + wn*32 + f*16],
                                    acc[i][f], 132, wmma::mem_row_major);
    __syncthreads();

    if (mode == 1){
#pragma unroll
        for (int j=0;j<16;j++){
            int idx = tid + j*256;
            int r = idx >> 5, c4 = (idx & 31)*4;
            float4 b4 = *(const float4*)&bias[n0 + c4];
            float4 v;
            v.x = Cs[r*132+c4+0] + b4.x;
            v.y = Cs[r*132+c4+1] + b4.y;
            v.z = Cs[r*132+c4+2] + b4.z;
            v.w = Cs[r*132+c4+3] + b4.w;
            *(float4*)&outp[(size_t)(m0+r)*EMBED + n0 + c4] = v;
        }
    } else {
        const int three = n0 >> 10;
        __half* dst0 = (three == 0) ? g_Qh : (three == 1) ? g_Kh : g_Vh;
#pragma unroll
        for (int j=0;j<16;j++){
            int idx = tid + j*256;
            int r = idx >> 5, c4 = (idx & 31)*4;
            int n = n0 + c4;
            int h = (n & 1023) >> 6, d0 = n & 63;
            int row = m0 + r;
            int bb = row >> 11, s0 = row & 2047;
            float4 b4 = *(const float4*)&bias[n];
            __half2 h0 = __floats2half2_rn(Cs[r*132+c4+0] + b4.x, Cs[r*132+c4+1] + b4.y);
            __half2 h1 = __floats2half2_rn(Cs[r*132+c4+2] + b4.z, Cs[r*132+c4+3] + b4.w);
            __half2* dp = (__half2*)&dst0[((size_t)(bb*NHEADS + h)*SEQ + s0)*HDIM + d0];
            dp[0] = h0; dp[1] = h1;
        }
    }
}

// ===========================================================================
// Flash attention: Q tile 64, KEY TILE 128 (16 iterations), fp16 wmma,
// cp.async prefetch (K and V in separate groups), mask skipped via g_flags.
// smem bytes: Qh 64x72h @0 (9216), Kh 128x72h @9216 (18432),
//             Vh 128x72h @27648 (18432), Ph 64x136h @46080 (17408),
//             Ssf 64x132f @63488 (33792; PV result overlays it). Total 97280.
// ===========================================================================
#define AQ  0
#define AK  9216
#define AVV 27648
#define AP  46080
#define ASS 63488
#define ATT_SMEM 97280

__global__ __launch_bounds__(256,2) void attn_kernel(const int* __restrict__ mask)
{
    extern __shared__ char smc[];
    const uint32_t sb = smem_u32(smc);
    __half* Qh = (__half*)(smc + AQ);
    __half* Kh = (__half*)(smc + AK);
    __half* Vh = (__half*)(smc + AVV);
    __half* Ph = (__half*)(smc + AP);
    float*  Ssf = (float*)(smc + ASS);

    const int qb = blockIdx.x, h = blockIdx.y, bb = blockIdx.z;
    const int tid = threadIdx.x, wid = tid >> 5;
    const int wm = wid & 3, wn = wid >> 2;
    const int trow = tid >> 2, tseg = tid & 3;

    const __half* Qg = g_Qh + ((size_t)(bb*NHEADS + h)*SEQ + qb*64)*HDIM;
    const __half* Kg = g_Kh +  (size_t)(bb*NHEADS + h)*SEQ*HDIM;
    const __half* Vg = g_Vh +  (size_t)(bb*NHEADS + h)*SEQ*HDIM;
    const int*    Mg = mask +  ((size_t)bb*SEQ + qb*64)*SEQ;
    const int*    Fg = g_flags + (bb*32 + qb)*16;

    // prologue: stage Q (64x64h), K0, V0 (128x64h each)
#pragma unroll
    for (int j=0;j<2;j++){
        int idx = tid + j*256;
        int r = idx >> 3, c8 = (idx & 7)*8;
        cpa16(sb + AQ + (r*72 + c8)*2, &Qg[(size_t)r*HDIM + c8]);
    }
#pragma unroll
    for (int j=0;j<4;j++){
        int idx = tid + j*256;
        int r = idx >> 3, c8 = (idx & 7)*8;
        cpa16(sb + AK  + (r*72 + c8)*2, &Kg[(size_t)r*HDIM + c8]);
        cpa16(sb + AVV + (r*72 + c8)*2, &Vg[(size_t)r*HDIM + c8]);
    }
    CPA_COMMIT();
    CPA_WAIT(0);
    __syncthreads();

    float o[16];
#pragma unroll
    for (int j=0;j<16;j++) o[j]=0.f;
    float m_i = -1e30f, l_i = 0.f;
    const float CE = 0.18033688011112042f;   // log2(e)/sqrt(64)

    for (int kt = 0; kt < SEQ/128; kt++){
        const int k0 = kt*128;

        // S[64,128] = Q @ K^T : warp tile 16(M) x 64(N), B col_major
        {
            wmma::fragment<wmma::accumulator,16,16,16,float> sacc[4];
#pragma unroll
            for (int f=0;f<4;f++) wmma::fill_fragment(sacc[f], 0.f);
#pragma unroll
            for (int k16=0;k16<64;k16+=16){
                wmma::fragment<wmma::matrix_a,16,16,16,__half,wmma::row_major> af;
                wmma::fragment<wmma::matrix_b,16,16,16,__half,wmma::col_major> bf;
                wmma::load_matrix_sync(af, &Qh[(wm*16)*72 + k16], 72);
#pragma unroll
                for (int f=0;f<4;f++){
                    wmma::load_matrix_sync(bf, &Kh[(wn*64 + f*16)*72 + k16], 72);
                    wmma::mma_sync(sacc[f], af, bf, sacc[f]);
                }
            }
#pragma unroll
            for (int f=0;f<4;f++)
                wmma::store_matrix_sync(&Ssf[(wm*16)*132 + wn*64 + f*16], sacc[f],
                                        132, wmma::mem_row_major);
        }
        __syncthreads();                                  // [1] S visible; Kh free

        // prefetch next K (group A)
        if (kt + 1 < SEQ/128){
            const int kn = k0 + 128;
#pragma unroll
            for (int j=0;j<4;j++){
                int idx = tid + j*256;
                int r = idx >> 3, c8 = (idx & 7)*8;
                cpa16(sb + AK + (r*72 + c8)*2, &Kg[(size_t)(kn+r)*HDIM + c8]);
            }
            CPA_COMMIT();
        }

        // online softmax: row trow, cols tseg*32..+31 (flag skips mask)
        {
            float s[32];
            const float* srow = &Ssf[trow*132 + tseg*32];
            if (Fg[kt]){
#pragma unroll
                for (int j4=0;j4<8;j4++){
                    float4 sv = *(const float4*)&srow[j4*4];
                    s[j4*4+0]=sv.x; s[j4*4+1]=sv.y; s[j4*4+2]=sv.z; s[j4*4+3]=sv.w;
                }
            } else {
                const int* mrow = Mg + (size_t)trow*SEQ + k0 + tseg*32;
#pragma unroll
                for (int j4=0;j4<8;j4++){
                    float4 sv = *(const float4*)&srow[j4*4];
                    int4   mv = *(const int4*)&mrow[j4*4];
                    s[j4*4+0] = mv.x ? sv.x : -1e30f;
                    s[j4*4+1] = mv.y ? sv.y : -1e30f;
                    s[j4*4+2] = mv.z ? sv.z : -1e30f;
                    s[j4*4+3] = mv.w ? sv.w : -1e30f;
                }
            }
            float rm = s[0];
#pragma unroll
            for (int j=1;j<32;j++) rm = fmaxf(rm, s[j]);
            rm = fmaxf(rm, __shfl_xor_sync(0xffffffffu, rm, 1));
            rm = fmaxf(rm, __shfl_xor_sync(0xffffffffu, rm, 2));
            const float mn = fmaxf(m_i, rm);
            const float alpha = ex2a((m_i - mn)*CE);
            m_i = mn;
            float rs = 0.f;
            __half2* prow2 = (__half2*)&Ph[trow*136 + tseg*32];
#pragma unroll
            for (int j2=0;j2<16;j2++){
                float p0 = ex2a((s[j2*2+0] - mn)*CE);
                float p1 = ex2a((s[j2*2+1] - mn)*CE);
                __half2 hp = __floats2half2_rn(p0, p1);
                prow2[j2] = hp;
                float2 bk = __half22float2(hp);           // l matches MMA's P
                rs += bk.x + bk.y;
            }
            rs += __shfl_xor_sync(0xffffffffu, rs, 1);
            rs += __shfl_xor_sync(0xffffffffu, rs, 2);
            l_i = l_i*alpha + rs;
#pragma unroll
            for (int j=0;j<16;j++) o[j] *= alpha;
        }
        __syncthreads();                                  // [2] P visible; Ssf free

        // PV[64,64] = P @ V : warp tile 16(M) x 32(N); result overlays Ssf
        {
            wmma::fragment<wmma::accumulator,16,16,16,float> pacc[2];
            wmma::fill_fragment(pacc[0], 0.f);
            wmma::fill_fragment(pacc[1], 0.f);
            const int wn2 = wid >> 2;                     // 0..1
#pragma unroll
            for (int k16=0;k16<128;k16+=16){
                wmma::fragment<wmma::matrix_a,16,16,16,__half,wmma::row_major> af;
                wmma::fragment<wmma::matrix_b,16,16,16,__half,wmma::row_major> bf[2];
                wmma::load_matrix_sync(af, &Ph[(wm*16)*136 + k16], 136);
                wmma::load_matrix_sync(bf[0], &Vh[k16*72 + wn2*32 +  0], 72);
                wmma::load_matrix_sync(bf[1], &Vh[k16*72 + wn2*32 + 16], 72);
                wmma::mma_sync(pacc[0], af, bf[0], pacc[0]);
                wmma::mma_sync(pacc[1], af, bf[1], pacc[1]);
            }
            wmma::store_matrix_sync(&Ssf[(wm*16)*132 + wn2*32 +  0], pacc[0], 132, wmma::mem_row_major);
            wmma::store_matrix_sync(&Ssf[(wm*16)*132 + wn2*32 + 16], pacc[1], 132, wmma::mem_row_major);
        }
        __syncthreads();                                  // [3] PV visible; Vh free

        // prefetch next V (group B)
        if (kt + 1 < SEQ/128){
            const int kn = k0 + 128;
#pragma unroll
            for (int j=0;j<4;j++){
                int idx = tid + j*256;
                int r = idx >> 3, c8 = (idx & 7)*8;
                cpa16(sb + AVV + (r*72 + c8)*2, &Vg[(size_t)(kn+r)*HDIM + c8]);
            }
            CPA_COMMIT();
        }

        // O accumulate from overlay
        {
            const float* pv = &Ssf[trow*132 + tseg*16];
#pragma unroll
            for (int j=0;j<16;j++) o[j] += pv[j];
        }
        if (kt + 1 < SEQ/128) CPA_WAIT(0);
        __syncthreads();                                  // [4] K/V ready; Ssf free
    }

    // writeout: g_Oh (b,s,e) half, e = h*64 + d
    const float inv = 1.0f / l_i;
    const int qrow = qb*64 + trow;
    __half2* dst = (__half2*)&g_Oh[((size_t)bb*SEQ + qrow)*EMBED + h*HDIM + tseg*16];
#pragma unroll
    for (int j2=0;j2<8;j2++)
        dst[j2] = __floats2half2_rn(o[j2*2]*inv, o[j2*2+1]*inv);
}

// ---------------------------------------------------------------------------
extern "C" void kernel_launch(void* const* d_in, const int* in_sizes, int n_in,
                              void* d_out, int out_size)
{
    const float* x     = (const float*)d_in[0];
    const int*   mask  = (const int*)  d_in[1];
    const float* w_qkv = (const float*)d_in[2];
    const float* b_qkv = (const float*)d_in[3];
    const float* w_out = (const float*)d_in[4];
    const float* b_out = (const float*)d_in[5];
    float* out = (float*)d_out;

    cudaFuncSetAttribute(proj_gemm,  cudaFuncAttributeMaxDynamicSharedMemorySize, PROJ_SMEM);
    cudaFuncSetAttribute(attn_kernel,cudaFuncAttributeMaxDynamicSharedMemorySize, ATT_SMEM);

    __half *x16, *w1h, *w2h, *oh;
    cudaGetSymbolAddress((void**)&x16, g_X16);
    cudaGetSymbolAddress((void**)&w1h, g_W1h);
    cudaGetSymbolAddress((void**)&w2h, g_W2h);
    cudaGetSymbolAddress((void**)&oh,  g_Oh);

    f2h<<<(MROWS*EMBED/8 + 255)/256, 256>>>(x,     x16, MROWS*EMBED/8);
    f2h<<<(EMBED*3*EMBED/8 + 255)/256, 256>>>(w_qkv, w1h, EMBED*3*EMBED/8);
    f2h<<<(EMBED*EMBED/8 + 255)/256, 256>>>(w_out,  w2h, EMBED*EMBED/8);
    mask_scan<<<dim3(16, 32, BATCH), 256>>>(mask);

    proj_gemm <<<dim3(3*EMBED/128, MROWS/128), 256, PROJ_SMEM>>>(x16, w1h, b_qkv, nullptr, 3*EMBED, 0);
    attn_kernel<<<dim3(SEQ/64, NHEADS, BATCH), 256, ATT_SMEM>>>(mask);
    proj_gemm <<<dim3(EMBED/128, MROWS/128), 256, PROJ_SMEM>>>(oh, w2h, b_out, out, EMBED, 1);
}